// round 8
// baseline (speedup 1.0000x reference)
#include <cuda_runtime.h>
#include <cstdint>
#include <math.h>

#define BATCH 4
#define C 512
#define HW 4096
#define G 32
#define CPG 16
#define EPS 1e-5f

// GEMM tiling
#define BM 128
#define BN 256
#define BK 32
#define STAGES 3
#define PAD 36                                   // floats per smem row (144B, 16B aligned, conflict-free)
#define STAGE_FLOATS ((BM + BN) * PAD)           // 13824
#define SMEM_BYTES (STAGES * STAGE_FLOATS * 4)   // 165888

// Scratch (static device memory — no allocations)
__device__ float g_ht [(size_t)BATCH * HW * C];      // groupnorm out, transposed [HW, C] (tf32)
__device__ float g_qkt[(size_t)BATCH * HW * 2 * C];  // q^T | k^T interleaved [HW, 2C] (tf32)
__device__ float g_v  [(size_t)BATCH * C * HW];      // v [C, HW] (tf32)
__device__ float g_s  [(size_t)BATCH * HW * HW];     // scores / attn [HWq, HWk]
__device__ float g_ot [(size_t)BATCH * HW * C];      // attn out, transposed [HW, C] (tf32)
__device__ float g_wr [(size_t)4 * C * C];           // tf32-rounded weights: qw, kw, vw, pw
__device__ float g_qkb[2 * C];                       // combined qb|kb

// ---------------------------------------------------------------------------
// helpers
// ---------------------------------------------------------------------------
__device__ __forceinline__ uint32_t smem_u32(const void* p) {
    uint32_t a;
    asm("{ .reg .u64 t; cvta.to.shared.u64 t, %1; cvt.u32.u64 %0, t; }" : "=r"(a) : "l"(p));
    return a;
}

__device__ __forceinline__ uint32_t f2tf32(float f) {
    uint32_t u;
    asm("cvt.rna.tf32.f32 %0, %1;" : "=r"(u) : "f"(f));
    return u;
}
__device__ __forceinline__ float rnd_tf32(float f) { return __uint_as_float(f2tf32(f)); }

__device__ __forceinline__ void cp16(uint32_t dst, const void* src) {
    asm volatile("cp.async.cg.shared.global [%0], [%1], 16;" :: "r"(dst), "l"(src));
}

__device__ __forceinline__ void mma8(float* c, const uint32_t* a, const uint32_t* b) {
    asm volatile(
        "mma.sync.aligned.m16n8k8.row.col.f32.tf32.tf32.f32 "
        "{%0,%1,%2,%3}, {%4,%5,%6,%7}, {%8,%9}, {%0,%1,%2,%3};"
        : "+f"(c[0]), "+f"(c[1]), "+f"(c[2]), "+f"(c[3])
        : "r"(a[0]), "r"(a[1]), "r"(a[2]), "r"(a[3]), "r"(b[0]), "r"(b[1]));
}

// ---------------------------------------------------------------------------
// tf32 mma.sync GEMM: D[m,n] = alpha * sum_k A[m,k]*B[n,k] (+bias) (+res)
// A: [M,K] rows stride ldA, B: [N,K] rows stride ldB, out: [M,N] row-major.
// Block tile 128x256, 512 threads (16 warps, 4x4 grid of 32x64 warp tiles),
// BK=32, 3-stage cp.async pipeline. M%128==0, N%256==0, K%32==0, K/32>=3.
// Operands must be tf32-representable (pre-rounded) for exact tf32 math.
// ---------------------------------------------------------------------------
template <bool BROW, bool BCOL, bool RES, bool RND>
__global__ void __launch_bounds__(512, 1) tc_gemm(
    const float* __restrict__ A, const float* __restrict__ B,
    const float* __restrict__ bias, const float* __restrict__ res,
    float* __restrict__ Cout, int M, int N, int K, int ldA, int ldB, float alpha,
    size_t sA, size_t sB, size_t sC, size_t sRes) {
    extern __shared__ float smf[];
    const int tid = threadIdx.x;
    const int wid = tid >> 5, lane = tid & 31;
    const int wm = wid >> 2, wn = wid & 3;      // warp grid 4 (M) x 4 (N)
    const int gq = lane >> 2, tq = lane & 3;    // quad decomposition
    const int bm = blockIdx.y * BM;
    const int bn = blockIdx.x * BN;

    A += (size_t)blockIdx.z * sA;
    B += (size_t)blockIdx.z * sB;
    Cout += (size_t)blockIdx.z * sC;
    if (RES) res += (size_t)blockIdx.z * sRes;

    const uint32_t sb = smem_u32(smf);

    float acc[2][8][4];
#pragma unroll
    for (int i = 0; i < 2; i++)
#pragma unroll
        for (int j = 0; j < 8; j++)
#pragma unroll
            for (int l = 0; l < 4; l++) acc[i][j][l] = 0.f;

    const int nchunk = K / BK;

    // stage loader: A 1024 float4, B 2048 float4 over 512 threads (6 cp16 each)
    auto load_stage = [&](int s, int c) {
        const int k0 = c * BK;
        const uint32_t st = sb + (uint32_t)(s * STAGE_FLOATS) * 4u;
#pragma unroll
        for (int t = 0; t < 2; t++) {
            const int i = tid + t * 512;
            const int row = i >> 3, q = i & 7;
            cp16(st + (uint32_t)(row * PAD + q * 4) * 4u,
                 &A[(size_t)(bm + row) * ldA + k0 + q * 4]);
        }
        const uint32_t stB = st + (uint32_t)(BM * PAD) * 4u;
#pragma unroll
        for (int t = 0; t < 4; t++) {
            const int i = tid + t * 512;
            const int row = i >> 3, q = i & 7;
            cp16(stB + (uint32_t)(row * PAD + q * 4) * 4u,
                 &B[(size_t)(bn + row) * ldB + k0 + q * 4]);
        }
    };

#pragma unroll
    for (int s = 0; s < STAGES - 1; s++) {
        load_stage(s, s);
        asm volatile("cp.async.commit_group;");
    }

    for (int c = 0; c < nchunk; c++) {
        asm volatile("cp.async.wait_group %0;" :: "n"(STAGES - 2));
        __syncthreads();

        const int nc = c + STAGES - 1;
        if (nc < nchunk) load_stage(nc % STAGES, nc);
        asm volatile("cp.async.commit_group;");

        const float* st = smf + (c % STAGES) * STAGE_FLOATS;
        const float* As = st;
        const float* Bs = st + BM * PAD;
#pragma unroll
        for (int k8 = 0; k8 < BK / 8; k8++) {
            uint32_t af[2][4], bf[8][2];
#pragma unroll
            for (int ms = 0; ms < 2; ms++) {
                const float* ap = As + (wm * 32 + ms * 16 + gq) * PAD + k8 * 8 + tq;
                af[ms][0] = __float_as_uint(ap[0]);
                af[ms][1] = __float_as_uint(ap[8 * PAD]);
                af[ms][2] = __float_as_uint(ap[4]);
                af[ms][3] = __float_as_uint(ap[8 * PAD + 4]);
            }
#pragma unroll
            for (int ns = 0; ns < 8; ns++) {
                const float* bp = Bs + (wn * 64 + ns * 8 + gq) * PAD + k8 * 8 + tq;
                bf[ns][0] = __float_as_uint(bp[0]);
                bf[ns][1] = __float_as_uint(bp[4]);
            }
#pragma unroll
            for (int ms = 0; ms < 2; ms++)
#pragma unroll
                for (int ns = 0; ns < 8; ns++) mma8(acc[ms][ns], af[ms], bf[ns]);
        }
    }

    // epilogue
#pragma unroll
    for (int ms = 0; ms < 2; ms++) {
        const int r0 = bm + wm * 32 + ms * 16 + gq;
        const int r1 = r0 + 8;
        const float bv0 = BROW ? bias[r0] : 0.f;
        const float bv1 = BROW ? bias[r1] : 0.f;
#pragma unroll
        for (int ns = 0; ns < 8; ns++) {
            const int col = bn + wn * 64 + ns * 8 + tq * 2;
            float2 o0, o1;
            o0.x = alpha * acc[ms][ns][0] + bv0;
            o0.y = alpha * acc[ms][ns][1] + bv0;
            o1.x = alpha * acc[ms][ns][2] + bv1;
            o1.y = alpha * acc[ms][ns][3] + bv1;
            if (BCOL) {
                const float bc0 = bias[col], bc1 = bias[col + 1];
                o0.x += bc0; o0.y += bc1;
                o1.x += bc0; o1.y += bc1;
            }
            if (RES) {
                const float2 q0 = *reinterpret_cast<const float2*>(&res[(size_t)r0 * N + col]);
                const float2 q1 = *reinterpret_cast<const float2*>(&res[(size_t)r1 * N + col]);
                o0.x += q0.x; o0.y += q0.y;
                o1.x += q1.x; o1.y += q1.y;
            }
            if (RND) {
                o0.x = rnd_tf32(o0.x); o0.y = rnd_tf32(o0.y);
                o1.x = rnd_tf32(o1.x); o1.y = rnd_tf32(o1.y);
            }
            *reinterpret_cast<float2*>(&Cout[(size_t)r0 * N + col]) = o0;
            *reinterpret_cast<float2*>(&Cout[(size_t)r1 * N + col]) = o1;
        }
    }
}

// ---------------------------------------------------------------------------
// tf32-round the four weight matrices into g_wr
// ---------------------------------------------------------------------------
__global__ void __launch_bounds__(256) round_w(const float* __restrict__ qw,
                                               const float* __restrict__ kw,
                                               const float* __restrict__ vw,
                                               const float* __restrict__ pw,
                                               float* __restrict__ o) {
    const int i = blockIdx.x * 256 + threadIdx.x;  // C*C = 262144 total
    o[i] = rnd_tf32(qw[i]);
    o[C * C + i] = rnd_tf32(kw[i]);
    o[2 * C * C + i] = rnd_tf32(vw[i]);
    o[3 * C * C + i] = rnd_tf32(pw[i]);
}

__global__ void qkb_kernel(const float* __restrict__ qb, const float* __restrict__ kb,
                           float* __restrict__ o) {
    const int i = threadIdx.x;  // 512
    o[i] = qb[i];
    o[C + i] = kb[i];
}

// ---------------------------------------------------------------------------
// GroupNorm -> transposed, tf32-rounded output hT [B, HW, C]
// ---------------------------------------------------------------------------
__global__ void __launch_bounds__(512) gn_kernel(const float* __restrict__ x,
                                                 const float* __restrict__ w,
                                                 const float* __restrict__ b,
                                                 float* __restrict__ hT) {
    const int batch = blockIdx.x / G;
    const int g = blockIdx.x % G;
    const float* xp = x + ((size_t)batch * C + (size_t)g * CPG) * HW;

    float sum = 0.f, sq = 0.f;
    for (int i = threadIdx.x; i < CPG * HW; i += blockDim.x) {
        const float v = xp[i];
        sum += v; sq += v * v;
    }
    __shared__ float s1[32], s2[32];
#pragma unroll
    for (int o = 16; o; o >>= 1) {
        sum += __shfl_xor_sync(~0u, sum, o);
        sq += __shfl_xor_sync(~0u, sq, o);
    }
    const int lane = threadIdx.x & 31, wid = threadIdx.x >> 5;
    if (lane == 0) { s1[wid] = sum; s2[wid] = sq; }
    __syncthreads();
    if (wid == 0) {
        sum = lane < 16 ? s1[lane] : 0.f;
        sq = lane < 16 ? s2[lane] : 0.f;
#pragma unroll
        for (int o = 16; o; o >>= 1) {
            sum += __shfl_xor_sync(~0u, sum, o);
            sq += __shfl_xor_sync(~0u, sq, o);
        }
        if (lane == 0) {
            const float inv_n = 1.f / (float)(CPG * HW);
            const float m = sum * inv_n;
            const float var = sq * inv_n - m * m;
            s1[0] = m;
            s2[0] = rsqrtf(var + EPS);
        }
    }
    __syncthreads();
    const float m = s1[0], r = s2[0];

    float ws[CPG], bs[CPG];
#pragma unroll
    for (int j = 0; j < CPG; j++) {
        const float wj = w[g * CPG + j];
        ws[j] = wj * r;
        bs[j] = b[g * CPG + j] - m * wj * r;
    }
    for (int p = threadIdx.x; p < HW; p += blockDim.x) {
        float o[CPG];
#pragma unroll
        for (int j = 0; j < CPG; j++) o[j] = rnd_tf32(xp[(size_t)j * HW + p] * ws[j] + bs[j]);
        float* dst = hT + ((size_t)batch * HW + p) * C + g * CPG;
#pragma unroll
        for (int j = 0; j < CPG; j += 4)
            *reinterpret_cast<float4*>(dst + j) = make_float4(o[j], o[j + 1], o[j + 2], o[j + 3]);
    }
}

// ---------------------------------------------------------------------------
// Row softmax over 4096 elements, in place; float4 I/O; output tf32-rounded.
// ---------------------------------------------------------------------------
__global__ void __launch_bounds__(256) softmax_kernel(float* __restrict__ s) {
    float4* row = reinterpret_cast<float4*>(s + (size_t)blockIdx.x * HW);  // 1024 float4
    const int t = threadIdx.x;
    float4 v[4];
    float mx = -1e30f;
#pragma unroll
    for (int i = 0; i < 4; i++) {
        v[i] = row[t + i * 256];
        mx = fmaxf(fmaxf(fmaxf(v[i].x, v[i].y), fmaxf(v[i].z, v[i].w)), mx);
    }
    __shared__ float shm[8], shs[8];
#pragma unroll
    for (int o = 16; o; o >>= 1) mx = fmaxf(mx, __shfl_xor_sync(~0u, mx, o));
    const int lane = t & 31, wid = t >> 5;
    if (lane == 0) shm[wid] = mx;
    __syncthreads();
    mx = shm[0];
#pragma unroll
    for (int i = 1; i < 8; i++) mx = fmaxf(mx, shm[i]);
    float sum = 0.f;
#pragma unroll
    for (int i = 0; i < 4; i++) {
        v[i].x = __expf(v[i].x - mx); v[i].y = __expf(v[i].y - mx);
        v[i].z = __expf(v[i].z - mx); v[i].w = __expf(v[i].w - mx);
        sum += (v[i].x + v[i].y) + (v[i].z + v[i].w);
    }
#pragma unroll
    for (int o = 16; o; o >>= 1) sum += __shfl_xor_sync(~0u, sum, o);
    if (lane == 0) shs[wid] = sum;
    __syncthreads();
    sum = 0.f;
#pragma unroll
    for (int i = 0; i < 8; i++) sum += shs[i];
    const float inv = 1.f / sum;
#pragma unroll
    for (int i = 0; i < 4; i++) {
        float4 o;
        o.x = rnd_tf32(v[i].x * inv); o.y = rnd_tf32(v[i].y * inv);
        o.z = rnd_tf32(v[i].z * inv); o.w = rnd_tf32(v[i].w * inv);
        row[t + i * 256] = o;
    }
}

// ---------------------------------------------------------------------------
extern "C" void kernel_launch(void* const* d_in, const int* in_sizes, int n_in,
                              void* d_out, int out_size) {
    const float* x   = (const float*)d_in[0];
    const float* gnw = (const float*)d_in[1];
    const float* gnb = (const float*)d_in[2];
    const float* qw  = (const float*)d_in[3];
    const float* qb  = (const float*)d_in[4];
    const float* kw  = (const float*)d_in[5];
    const float* kb  = (const float*)d_in[6];
    const float* vw  = (const float*)d_in[7];
    const float* vb  = (const float*)d_in[8];
    const float* pw  = (const float*)d_in[9];
    const float* pb  = (const float*)d_in[10];
    float* out = (float*)d_out;

    float *ht, *qkt, *v, *s, *ot, *wr, *qkb;
    cudaGetSymbolAddress((void**)&ht, g_ht);
    cudaGetSymbolAddress((void**)&qkt, g_qkt);
    cudaGetSymbolAddress((void**)&v, g_v);
    cudaGetSymbolAddress((void**)&s, g_s);
    cudaGetSymbolAddress((void**)&ot, g_ot);
    cudaGetSymbolAddress((void**)&wr, g_wr);
    cudaGetSymbolAddress((void**)&qkb, g_qkb);

    cudaFuncSetAttribute(tc_gemm<false, true,  false, true >, cudaFuncAttributeMaxDynamicSharedMemorySize, SMEM_BYTES);
    cudaFuncSetAttribute(tc_gemm<true,  false, false, true >, cudaFuncAttributeMaxDynamicSharedMemorySize, SMEM_BYTES);
    cudaFuncSetAttribute(tc_gemm<false, false, false, false>, cudaFuncAttributeMaxDynamicSharedMemorySize, SMEM_BYTES);
    cudaFuncSetAttribute(tc_gemm<false, false, false, true >, cudaFuncAttributeMaxDynamicSharedMemorySize, SMEM_BYTES);
    cudaFuncSetAttribute(tc_gemm<true,  false, true,  false>, cudaFuncAttributeMaxDynamicSharedMemorySize, SMEM_BYTES);

    const size_t sHC = (size_t)HW * C;
    const size_t sQK = (size_t)HW * 2 * C;
    const size_t sS = (size_t)HW * HW;
    const float scale = 0.044194173824159216f;  // 512^-0.5

    // 0) tf32-round weights, combined qk bias; 1) GroupNorm -> hT (rounded)
    round_w<<<C * C / 256, 256>>>(qw, kw, vw, pw, wr);
    qkb_kernel<<<1, C>>>(qb, kb, qkb);
    gn_kernel<<<BATCH * G, 512>>>(x, gnw, gnb, ht);

    const float* vwr = wr + (size_t)2 * C * C;
    const float* pwr = wr + (size_t)3 * C * C;

    dim3 blk(512);
    // 2) [qT|kT] = hT @ [qw;kw]^T + bias(col):  M=HW, N=2C, K=C
    dim3 g1(2 * C / BN, HW / BM, BATCH);
    tc_gemm<false, true, false, true><<<g1, blk, SMEM_BYTES>>>(
        ht, wr, qkb, nullptr, qkt, HW, 2 * C, C, C, C, 1.f, sHC, 0, sQK, 0);
    //    v = W @ h + bias(row):  M=C, N=HW, K=C   (B = hT)
    dim3 g2(HW / BN, C / BM, BATCH);
    tc_gemm<true, false, false, true><<<g2, blk, SMEM_BYTES>>>(
        vwr, ht, vb, nullptr, v, C, HW, C, C, C, 1.f, 0, sHC, sHC, 0);

    // 3) scores = qT @ kT^T * scale:  M=HW, N=HW, K=C  (A,B strided in qkt)
    dim3 g3(HW / BN, HW / BM, BATCH);
    tc_gemm<false, false, false, false><<<g3, blk, SMEM_BYTES>>>(
        qkt, qkt + C, nullptr, nullptr, s, HW, HW, C, 2 * C, 2 * C, scale, sQK, sQK, sS, 0);

    // 4) softmax rows (rounded output)
    softmax_kernel<<<BATCH * HW, 256>>>(s);

    // 5) oT = attn @ v^T:  M=HW(q), N=C(d), K=HW(k)
    dim3 g5(C / BN, HW / BM, BATCH);
    tc_gemm<false, false, false, true><<<g5, blk, SMEM_BYTES>>>(
        s, v, nullptr, nullptr, ot, HW, C, HW, HW, HW, 1.f, sS, sHC, sHC, 0);

    // 6) out = x + pw @ o + pb:  M=C, N=HW, K=C  (B = oT)
    dim3 g6(HW / BN, C / BM, BATCH);
    tc_gemm<true, false, true, false><<<g6, blk, SMEM_BYTES>>>(
        pwr, ot, pb, x, out, C, HW, C, C, C, 1.f, 0, sHC, sHC, sHC);
}

// round 9
// speedup vs baseline: 1.8653x; 1.8653x over previous
#include <cuda_runtime.h>
#include <cuda_fp16.h>
#include <cstdint>
#include <math.h>

#define BATCH 4
#define C 512
#define HW 4096
#define G 32
#define CPG 16
#define EPS 1e-5f

// GEMM tiling (fp16 operands, fp32 accumulate)
#define BM 128
#define BN 256
#define BKH 64                                    // K halves per chunk (128 bytes)
#define STAGES 3
#define PADH 72                                   // halves per smem row (144B; bank stride 4 -> conflict-free)
#define STAGE_HALFS ((BM + BN) * PADH)            // 27648
#define SMEM_BYTES (STAGES * STAGE_HALFS * 2)     // 165888

// Scratch (static device memory — no allocations)
__device__ __half g_hth [(size_t)BATCH * HW * C];      // groupnorm out^T [HW, C]
__device__ __half g_qkth[(size_t)BATCH * HW * 2 * C];  // q^T | k^T [HW, 2C]
__device__ __half g_vh  [(size_t)BATCH * C * HW];      // v [C, HW]
__device__ float  g_s   [(size_t)BATCH * HW * HW];     // scores fp32 [HWq, HWk]
__device__ __half g_at  [(size_t)BATCH * HW * HW];     // attn fp16 [HWq, HWk]
__device__ __half g_oth [(size_t)BATCH * HW * C];      // attn out^T [HW, C]
__device__ __half g_wh  [(size_t)4 * C * C];           // fp16 weights: qw, kw, vw, pw
__device__ float  g_qkb[2 * C];                        // combined qb|kb

// ---------------------------------------------------------------------------
// helpers
// ---------------------------------------------------------------------------
__device__ __forceinline__ uint32_t smem_u32(const void* p) {
    uint32_t a;
    asm("{ .reg .u64 t; cvta.to.shared.u64 t, %1; cvt.u32.u64 %0, t; }" : "=r"(a) : "l"(p));
    return a;
}

__device__ __forceinline__ void cp16(uint32_t dst, const void* src) {
    asm volatile("cp.async.cg.shared.global [%0], [%1], 16;" :: "r"(dst), "l"(src));
}

__device__ __forceinline__ void mma16(float* c, const uint32_t* a, const uint32_t* b) {
    asm volatile(
        "mma.sync.aligned.m16n8k16.row.col.f32.f16.f16.f32 "
        "{%0,%1,%2,%3}, {%4,%5,%6,%7}, {%8,%9}, {%0,%1,%2,%3};"
        : "+f"(c[0]), "+f"(c[1]), "+f"(c[2]), "+f"(c[3])
        : "r"(a[0]), "r"(a[1]), "r"(a[2]), "r"(a[3]), "r"(b[0]), "r"(b[1]));
}

// ---------------------------------------------------------------------------
// fp16 mma.sync GEMM: D[m,n] = alpha * sum_k A[m,k]*B[n,k] (+bias) (+res)
// A: [M,K] half, rows stride ldA; B: [N,K] half, rows stride ldB.
// Out: [M,N] row-major, fp32 or fp16 (OUTH). Block tile 128x256, 256 threads
// (8 warps, 2x4 grid of 64x64 warp tiles), BKH=64, 3-stage cp.async pipeline.
// M%128==0, N%256==0, K%64==0, K/64>=3.
// ---------------------------------------------------------------------------
template <bool BROW, bool BCOL, bool RES, bool OUTH>
__global__ void __launch_bounds__(256, 1) hgemm(
    const __half* __restrict__ A, const __half* __restrict__ B,
    const float* __restrict__ bias, const float* __restrict__ res,
    void* __restrict__ CoutV, int M, int N, int K, int ldA, int ldB, float alpha,
    size_t sA, size_t sB, size_t sC, size_t sRes) {
    extern __shared__ __half smh[];
    const int tid = threadIdx.x;
    const int wid = tid >> 5, lane = tid & 31;
    const int wm = wid >> 2, wn = wid & 3;      // warp grid 2 (M) x 4 (N)
    const int gq = lane >> 2, tq = lane & 3;    // quad decomposition
    const int bm = blockIdx.y * BM;
    const int bn = blockIdx.x * BN;

    A += (size_t)blockIdx.z * sA;
    B += (size_t)blockIdx.z * sB;
    float* Cf = (float*)CoutV + (size_t)blockIdx.z * sC;
    __half* Ch = (__half*)CoutV + (size_t)blockIdx.z * sC;
    if (RES) res += (size_t)blockIdx.z * sRes;

    const uint32_t sb = smem_u32(smh);

    float acc[4][8][4];
#pragma unroll
    for (int i = 0; i < 4; i++)
#pragma unroll
        for (int j = 0; j < 8; j++)
#pragma unroll
            for (int l = 0; l < 4; l++) acc[i][j][l] = 0.f;

    const int nchunk = K / BKH;

    // stage loader: A 1024 cp16 + B 2048 cp16 over 256 threads (12 each)
    auto load_stage = [&](int s, int c) {
        const int k0 = c * BKH;
        const uint32_t st = sb + (uint32_t)(s * STAGE_HALFS) * 2u;
#pragma unroll
        for (int t = 0; t < 4; t++) {
            const int i = tid + t * 256;
            const int row = i >> 3, q = i & 7;
            cp16(st + (uint32_t)(row * PADH + q * 8) * 2u,
                 &A[(size_t)(bm + row) * ldA + k0 + q * 8]);
        }
        const uint32_t stB = st + (uint32_t)(BM * PADH) * 2u;
#pragma unroll
        for (int t = 0; t < 8; t++) {
            const int i = tid + t * 256;
            const int row = i >> 3, q = i & 7;
            cp16(stB + (uint32_t)(row * PADH + q * 8) * 2u,
                 &B[(size_t)(bn + row) * ldB + k0 + q * 8]);
        }
    };

#pragma unroll
    for (int s = 0; s < STAGES - 1; s++) {
        load_stage(s, s);
        asm volatile("cp.async.commit_group;");
    }

    for (int c = 0; c < nchunk; c++) {
        asm volatile("cp.async.wait_group %0;" :: "n"(STAGES - 2));
        __syncthreads();

        const int nc = c + STAGES - 1;
        if (nc < nchunk) load_stage(nc % STAGES, nc);
        asm volatile("cp.async.commit_group;");

        const __half* st = smh + (c % STAGES) * STAGE_HALFS;
        const __half* As = st;
        const __half* Bs = st + BM * PADH;
#pragma unroll
        for (int kk = 0; kk < BKH / 16; kk++) {
            uint32_t af[4][4], bf[8][2];
#pragma unroll
            for (int ms = 0; ms < 4; ms++) {
                const __half* ap = As + (wm * 64 + ms * 16 + gq) * PADH + kk * 16 + 2 * tq;
                af[ms][0] = *reinterpret_cast<const uint32_t*>(ap);
                af[ms][1] = *reinterpret_cast<const uint32_t*>(ap + 8 * PADH);
                af[ms][2] = *reinterpret_cast<const uint32_t*>(ap + 8);
                af[ms][3] = *reinterpret_cast<const uint32_t*>(ap + 8 * PADH + 8);
            }
#pragma unroll
            for (int ns = 0; ns < 8; ns++) {
                const __half* bp = Bs + (wn * 64 + ns * 8 + gq) * PADH + kk * 16 + 2 * tq;
                bf[ns][0] = *reinterpret_cast<const uint32_t*>(bp);
                bf[ns][1] = *reinterpret_cast<const uint32_t*>(bp + 8);
            }
#pragma unroll
            for (int ms = 0; ms < 4; ms++)
#pragma unroll
                for (int ns = 0; ns < 8; ns++) mma16(acc[ms][ns], af[ms], bf[ns]);
        }
    }

    // epilogue
#pragma unroll
    for (int ms = 0; ms < 4; ms++) {
        const int r0 = bm + wm * 64 + ms * 16 + gq;
        const int r1 = r0 + 8;
        const float bv0 = BROW ? bias[r0] : 0.f;
        const float bv1 = BROW ? bias[r1] : 0.f;
#pragma unroll
        for (int ns = 0; ns < 8; ns++) {
            const int col = bn + wn * 64 + ns * 8 + tq * 2;
            float2 o0, o1;
            o0.x = alpha * acc[ms][ns][0] + bv0;
            o0.y = alpha * acc[ms][ns][1] + bv0;
            o1.x = alpha * acc[ms][ns][2] + bv1;
            o1.y = alpha * acc[ms][ns][3] + bv1;
            if (BCOL) {
                const float bc0 = bias[col], bc1 = bias[col + 1];
                o0.x += bc0; o0.y += bc1;
                o1.x += bc0; o1.y += bc1;
            }
            if (RES) {
                const float2 q0 = *reinterpret_cast<const float2*>(&res[(size_t)r0 * N + col]);
                const float2 q1 = *reinterpret_cast<const float2*>(&res[(size_t)r1 * N + col]);
                o0.x += q0.x; o0.y += q0.y;
                o1.x += q1.x; o1.y += q1.y;
            }
            if (OUTH) {
                *reinterpret_cast<__half2*>(&Ch[(size_t)r0 * N + col]) = __floats2half2_rn(o0.x, o0.y);
                *reinterpret_cast<__half2*>(&Ch[(size_t)r1 * N + col]) = __floats2half2_rn(o1.x, o1.y);
            } else {
                *reinterpret_cast<float2*>(&Cf[(size_t)r0 * N + col]) = o0;
                *reinterpret_cast<float2*>(&Cf[(size_t)r1 * N + col]) = o1;
            }
        }
    }
}

// ---------------------------------------------------------------------------
// convert the four weight matrices to fp16 in g_wh (order: qw, kw, vw, pw)
// ---------------------------------------------------------------------------
__global__ void __launch_bounds__(256) conv_w(const float* __restrict__ qw,
                                              const float* __restrict__ kw,
                                              const float* __restrict__ vw,
                                              const float* __restrict__ pw,
                                              __half* __restrict__ o) {
    const int i = blockIdx.x * 256 + threadIdx.x;  // C*C total
    o[i] = __float2half_rn(qw[i]);
    o[C * C + i] = __float2half_rn(kw[i]);
    o[2 * C * C + i] = __float2half_rn(vw[i]);
    o[3 * C * C + i] = __float2half_rn(pw[i]);
}

__global__ void qkb_kernel(const float* __restrict__ qb, const float* __restrict__ kb,
                           float* __restrict__ o) {
    const int i = threadIdx.x;  // 512
    o[i] = qb[i];
    o[C + i] = kb[i];
}

// ---------------------------------------------------------------------------
// GroupNorm -> transposed fp16 output hT [B, HW, C]
// ---------------------------------------------------------------------------
__global__ void __launch_bounds__(512) gn_kernel(const float* __restrict__ x,
                                                 const float* __restrict__ w,
                                                 const float* __restrict__ b,
                                                 __half* __restrict__ hT) {
    const int batch = blockIdx.x / G;
    const int g = blockIdx.x % G;
    const float* xp = x + ((size_t)batch * C + (size_t)g * CPG) * HW;

    float sum = 0.f, sq = 0.f;
    for (int i = threadIdx.x; i < CPG * HW; i += blockDim.x) {
        const float v = xp[i];
        sum += v; sq += v * v;
    }
    __shared__ float s1[32], s2[32];
#pragma unroll
    for (int o = 16; o; o >>= 1) {
        sum += __shfl_xor_sync(~0u, sum, o);
        sq += __shfl_xor_sync(~0u, sq, o);
    }
    const int lane = threadIdx.x & 31, wid = threadIdx.x >> 5;
    if (lane == 0) { s1[wid] = sum; s2[wid] = sq; }
    __syncthreads();
    if (wid == 0) {
        sum = lane < 16 ? s1[lane] : 0.f;
        sq = lane < 16 ? s2[lane] : 0.f;
#pragma unroll
        for (int o = 16; o; o >>= 1) {
            sum += __shfl_xor_sync(~0u, sum, o);
            sq += __shfl_xor_sync(~0u, sq, o);
        }
        if (lane == 0) {
            const float inv_n = 1.f / (float)(CPG * HW);
            const float m = sum * inv_n;
            const float var = sq * inv_n - m * m;
            s1[0] = m;
            s2[0] = rsqrtf(var + EPS);
        }
    }
    __syncthreads();
    const float m = s1[0], r = s2[0];

    float ws[CPG], bs[CPG];
#pragma unroll
    for (int j = 0; j < CPG; j++) {
        const float wj = w[g * CPG + j];
        ws[j] = wj * r;
        bs[j] = b[g * CPG + j] - m * wj * r;
    }
    for (int p = threadIdx.x; p < HW; p += blockDim.x) {
        __half2 o[CPG / 2];
#pragma unroll
        for (int j = 0; j < CPG; j += 2)
            o[j / 2] = __floats2half2_rn(xp[(size_t)j * HW + p] * ws[j] + bs[j],
                                         xp[(size_t)(j + 1) * HW + p] * ws[j + 1] + bs[j + 1]);
        __half2* dst = reinterpret_cast<__half2*>(hT + ((size_t)batch * HW + p) * C + g * CPG);
#pragma unroll
        for (int j = 0; j < CPG / 2; j++) dst[j] = o[j];
    }
}

// ---------------------------------------------------------------------------
// Row softmax over 4096 fp32 scores -> fp16 attn.
// ---------------------------------------------------------------------------
__global__ void __launch_bounds__(256) softmax_kernel(const float* __restrict__ s,
                                                      __half* __restrict__ at) {
    const float4* row = reinterpret_cast<const float4*>(s + (size_t)blockIdx.x * HW);
    uint2* orow = reinterpret_cast<uint2*>(at + (size_t)blockIdx.x * HW);
    const int t = threadIdx.x;
    float4 v[4];
    float mx = -1e30f;
#pragma unroll
    for (int i = 0; i < 4; i++) {
        v[i] = row[t + i * 256];
        mx = fmaxf(fmaxf(fmaxf(v[i].x, v[i].y), fmaxf(v[i].z, v[i].w)), mx);
    }
    __shared__ float shm[8], shs[8];
#pragma unroll
    for (int o = 16; o; o >>= 1) mx = fmaxf(mx, __shfl_xor_sync(~0u, mx, o));
    const int lane = t & 31, wid = t >> 5;
    if (lane == 0) shm[wid] = mx;
    __syncthreads();
    mx = shm[0];
#pragma unroll
    for (int i = 1; i < 8; i++) mx = fmaxf(mx, shm[i]);
    float sum = 0.f;
#pragma unroll
    for (int i = 0; i < 4; i++) {
        v[i].x = __expf(v[i].x - mx); v[i].y = __expf(v[i].y - mx);
        v[i].z = __expf(v[i].z - mx); v[i].w = __expf(v[i].w - mx);
        sum += (v[i].x + v[i].y) + (v[i].z + v[i].w);
    }
#pragma unroll
    for (int o = 16; o; o >>= 1) sum += __shfl_xor_sync(~0u, sum, o);
    if (lane == 0) shs[wid] = sum;
    __syncthreads();
    sum = 0.f;
#pragma unroll
    for (int i = 0; i < 8; i++) sum += shs[i];
    const float inv = 1.f / sum;
#pragma unroll
    for (int i = 0; i < 4; i++) {
        const __half2 h01 = __floats2half2_rn(v[i].x * inv, v[i].y * inv);
        const __half2 h23 = __floats2half2_rn(v[i].z * inv, v[i].w * inv);
        uint2 o;
        o.x = *reinterpret_cast<const uint32_t*>(&h01);
        o.y = *reinterpret_cast<const uint32_t*>(&h23);
        orow[t + i * 256] = o;
    }
}

// ---------------------------------------------------------------------------
extern "C" void kernel_launch(void* const* d_in, const int* in_sizes, int n_in,
                              void* d_out, int out_size) {
    const float* x   = (const float*)d_in[0];
    const float* gnw = (const float*)d_in[1];
    const float* gnb = (const float*)d_in[2];
    const float* qw  = (const float*)d_in[3];
    const float* qb  = (const float*)d_in[4];
    const float* kw  = (const float*)d_in[5];
    const float* kb  = (const float*)d_in[6];
    const float* vw  = (const float*)d_in[7];
    const float* vb  = (const float*)d_in[8];
    const float* pw  = (const float*)d_in[9];
    const float* pb  = (const float*)d_in[10];
    float* out = (float*)d_out;

    __half *hth, *qkth, *vh, *at, *oth, *wh;
    float *s, *qkb;
    cudaGetSymbolAddress((void**)&hth, g_hth);
    cudaGetSymbolAddress((void**)&qkth, g_qkth);
    cudaGetSymbolAddress((void**)&vh, g_vh);
    cudaGetSymbolAddress((void**)&s, g_s);
    cudaGetSymbolAddress((void**)&at, g_at);
    cudaGetSymbolAddress((void**)&oth, g_oth);
    cudaGetSymbolAddress((void**)&wh, g_wh);
    cudaGetSymbolAddress((void**)&qkb, g_qkb);

    cudaFuncSetAttribute(hgemm<false, true,  false, true >, cudaFuncAttributeMaxDynamicSharedMemorySize, SMEM_BYTES);
    cudaFuncSetAttribute(hgemm<true,  false, false, true >, cudaFuncAttributeMaxDynamicSharedMemorySize, SMEM_BYTES);
    cudaFuncSetAttribute(hgemm<false, false, false, false>, cudaFuncAttributeMaxDynamicSharedMemorySize, SMEM_BYTES);
    cudaFuncSetAttribute(hgemm<false, false, false, true >, cudaFuncAttributeMaxDynamicSharedMemorySize, SMEM_BYTES);
    cudaFuncSetAttribute(hgemm<true,  false, true,  false>, cudaFuncAttributeMaxDynamicSharedMemorySize, SMEM_BYTES);

    const size_t sHC = (size_t)HW * C;
    const size_t sQK = (size_t)HW * 2 * C;
    const size_t sS = (size_t)HW * HW;
    const float scale = 0.044194173824159216f;  // 512^-0.5

    // 0) fp16 weights + combined qk bias; 1) GroupNorm -> hT (fp16)
    conv_w<<<C * C / 256, 256>>>(qw, kw, vw, pw, wh);
    qkb_kernel<<<1, C>>>(qb, kb, qkb);
    gn_kernel<<<BATCH * G, 512>>>(x, gnw, gnb, hth);

    const __half* vwh = wh + (size_t)2 * C * C;
    const __half* pwh = wh + (size_t)3 * C * C;

    dim3 blk(256);
    // 2) [qT|kT] = hT @ [qw;kw]^T + bias(col):  M=HW, N=2C, K=C
    dim3 g1(2 * C / BN, HW / BM, BATCH);
    hgemm<false, true, false, true><<<g1, blk, SMEM_BYTES>>>(
        hth, wh, qkb, nullptr, qkth, HW, 2 * C, C, C, C, 1.f, sHC, 0, sQK, 0);
    //    v = W @ h + bias(row):  M=C, N=HW, K=C
    dim3 g2(HW / BN, C / BM, BATCH);
    hgemm<true, false, false, true><<<g2, blk, SMEM_BYTES>>>(
        vwh, hth, vb, nullptr, vh, C, HW, C, C, C, 1.f, 0, sHC, sHC, 0);

    // 3) scores = qT @ kT^T * scale (fp32 out):  M=HW, N=HW, K=C
    dim3 g3(HW / BN, HW / BM, BATCH);
    hgemm<false, false, false, false><<<g3, blk, SMEM_BYTES>>>(
        qkth, qkth + C, nullptr, nullptr, s, HW, HW, C, 2 * C, 2 * C, scale, sQK, sQK, sS, 0);

    // 4) softmax rows -> fp16 attn
    softmax_kernel<<<BATCH * HW, 256>>>(s, at);

    // 5) oT = attn @ v^T:  M=HW(q), N=C(d), K=HW(k)
    dim3 g5(C / BN, HW / BM, BATCH);
    hgemm<false, false, false, true><<<g5, blk, SMEM_BYTES>>>(
        at, vh, nullptr, nullptr, oth, HW, C, HW, HW, HW, 1.f, sS, sHC, sHC, 0);

    // 6) out = x + pw @ o + pb:  M=C, N=HW, K=C
    dim3 g6(HW / BN, C / BM, BATCH);
    hgemm<true, false, true, false><<<g6, blk, SMEM_BYTES>>>(
        pwh, oth, pb, x, out, C, HW, C, C, C, 1.f, 0, sHC, sHC, sHC);
}

// round 10
// speedup vs baseline: 1.9149x; 1.0266x over previous
#include <cuda_runtime.h>
#include <cuda_fp16.h>
#include <cstdint>
#include <math.h>

#define BATCH 4
#define C 512
#define HW 4096
#define G 32
#define CPG 16
#define EPS 1e-5f

// GEMM tiling (fp16 operands, fp32 accumulate)
#define BM 128
#define BN 256
#define BKH 64                                    // K halves per chunk (128 bytes)
#define STAGES 3
#define PADH 72                                   // halves per smem row (144B; stride 36 words -> conflict-free)
#define STAGE_HALFS ((BM + BN) * PADH)            // 27648
#define SMEM_BYTES (STAGES * STAGE_HALFS * 2)     // 165888

// Scratch (static device memory — no allocations)
__device__ __half g_hth [(size_t)BATCH * HW * C];      // groupnorm out^T [HW, C]
__device__ __half g_qkth[(size_t)BATCH * HW * 2 * C];  // q^T | k^T [HW, 2C]
__device__ __half g_vh  [(size_t)BATCH * C * HW];      // v [C, HW]
__device__ float  g_s   [(size_t)BATCH * HW * HW];     // scores fp32 [HWq, HWk]
__device__ __half g_at  [(size_t)BATCH * HW * HW];     // attn fp16 [HWq, HWk]
__device__ __half g_oth [(size_t)BATCH * HW * C];      // attn out^T [HW, C]
__device__ __half g_wh  [(size_t)4 * C * C];           // fp16 weights: qw, kw, vw, pw
__device__ float  g_qkb[2 * C];                        // combined qb|kb

// ---------------------------------------------------------------------------
// helpers
// ---------------------------------------------------------------------------
__device__ __forceinline__ uint32_t smem_u32(const void* p) {
    uint32_t a;
    asm("{ .reg .u64 t; cvta.to.shared.u64 t, %1; cvt.u32.u64 %0, t; }" : "=r"(a) : "l"(p));
    return a;
}

__device__ __forceinline__ void cp16(uint32_t dst, const void* src) {
    asm volatile("cp.async.cg.shared.global [%0], [%1], 16;" :: "r"(dst), "l"(src));
}

__device__ __forceinline__ void mma16(float* c, const uint32_t* a, const uint32_t* b) {
    asm volatile(
        "mma.sync.aligned.m16n8k16.row.col.f32.f16.f16.f32 "
        "{%0,%1,%2,%3}, {%4,%5,%6,%7}, {%8,%9}, {%0,%1,%2,%3};"
        : "+f"(c[0]), "+f"(c[1]), "+f"(c[2]), "+f"(c[3])
        : "r"(a[0]), "r"(a[1]), "r"(a[2]), "r"(a[3]), "r"(b[0]), "r"(b[1]));
}

#define LDSM4(r0, r1, r2, r3, addr)                                             \
    asm volatile("ldmatrix.sync.aligned.m8n8.x4.shared.b16 {%0,%1,%2,%3}, [%4];" \
                 : "=r"(r0), "=r"(r1), "=r"(r2), "=r"(r3) : "r"(addr))

// ---------------------------------------------------------------------------
// fp16 mma.sync GEMM: D[m,n] = alpha * sum_k A[m,k]*B[n,k] (+bias) (+res)
// A: [M,K] half, rows stride ldA; B: [N,K] half, rows stride ldB.
// Out: [M,N] row-major, fp32 or fp16 (OUTH). Block tile 128x256, 256 threads
// (8 warps, 2x4 grid of 64x64 warp tiles), BKH=64, 3-stage cp.async pipeline,
// ldmatrix fragment loads, register double-buffered over k16 steps.
// M%128==0, N%256==0, K%64==0, K/64>=3.
// ---------------------------------------------------------------------------
template <bool BROW, bool BCOL, bool RES, bool OUTH>
__global__ void __launch_bounds__(256, 1) hgemm(
    const __half* __restrict__ A, const __half* __restrict__ B,
    const float* __restrict__ bias, const float* __restrict__ res,
    void* __restrict__ CoutV, int M, int N, int K, int ldA, int ldB, float alpha,
    size_t sA, size_t sB, size_t sC, size_t sRes) {
    extern __shared__ __half smh[];
    const int tid = threadIdx.x;
    const int wid = tid >> 5, lane = tid & 31;
    const int wm = wid >> 2, wn = wid & 3;      // warp grid 2 (M) x 4 (N)
    const int gq = lane >> 2, tq = lane & 3;    // quad decomposition
    const int lj = lane >> 3, lr = lane & 7;    // ldmatrix matrix id / row
    const int bm = blockIdx.y * BM;
    const int bn = blockIdx.x * BN;

    A += (size_t)blockIdx.z * sA;
    B += (size_t)blockIdx.z * sB;
    float* Cf = (float*)CoutV + (size_t)blockIdx.z * sC;
    __half* Ch = (__half*)CoutV + (size_t)blockIdx.z * sC;
    if (RES) res += (size_t)blockIdx.z * sRes;

    const uint32_t sb = smem_u32(smh);

    // per-lane ldmatrix byte offsets within a stage
    //  A matrices: j&1 -> +8 rows(m), j>>1 -> +8 k
    //  B matrices: j>>1 -> +8 rows(n), j&1 -> +8 k
    const uint32_t a_lane = ((uint32_t)((wm * 64 + (lj & 1) * 8 + lr) * PADH + (lj >> 1) * 8)) * 2u;
    const uint32_t b_lane = ((uint32_t)((wn * 64 + (lj >> 1) * 8 + lr) * PADH + (lj & 1) * 8)) * 2u
                            + (uint32_t)(BM * PADH) * 2u;

    float acc[4][8][4];
#pragma unroll
    for (int i = 0; i < 4; i++)
#pragma unroll
        for (int j = 0; j < 8; j++)
#pragma unroll
            for (int l = 0; l < 4; l++) acc[i][j][l] = 0.f;

    const int nchunk = K / BKH;

    // stage loader: A 1024 cp16 + B 2048 cp16 over 256 threads (12 each)
    auto load_stage = [&](int s, int c) {
        const int k0 = c * BKH;
        const uint32_t st = sb + (uint32_t)(s * STAGE_HALFS) * 2u;
#pragma unroll
        for (int t = 0; t < 4; t++) {
            const int i = tid + t * 256;
            const int row = i >> 3, q = i & 7;
            cp16(st + (uint32_t)(row * PADH + q * 8) * 2u,
                 &A[(size_t)(bm + row) * ldA + k0 + q * 8]);
        }
        const uint32_t stB = st + (uint32_t)(BM * PADH) * 2u;
#pragma unroll
        for (int t = 0; t < 8; t++) {
            const int i = tid + t * 256;
            const int row = i >> 3, q = i & 7;
            cp16(stB + (uint32_t)(row * PADH + q * 8) * 2u,
                 &B[(size_t)(bn + row) * ldB + k0 + q * 8]);
        }
    };

    uint32_t af[2][4][4], bf[2][8][2];

    auto load_frags = [&](uint32_t st, int kk, int buf) {
        const uint32_t ka = st + a_lane + (uint32_t)(kk * 16) * 2u;
        const uint32_t kb = st + b_lane + (uint32_t)(kk * 16) * 2u;
#pragma unroll
        for (int ms = 0; ms < 4; ms++)
            LDSM4(af[buf][ms][0], af[buf][ms][1], af[buf][ms][2], af[buf][ms][3],
                  ka + (uint32_t)(ms * 16 * PADH) * 2u);
#pragma unroll
        for (int p = 0; p < 4; p++)
            LDSM4(bf[buf][2 * p][0], bf[buf][2 * p][1], bf[buf][2 * p + 1][0], bf[buf][2 * p + 1][1],
                  kb + (uint32_t)(p * 16 * PADH) * 2u);
    };

#pragma unroll
    for (int s = 0; s < STAGES - 1; s++) {
        load_stage(s, s);
        asm volatile("cp.async.commit_group;");
    }

    for (int c = 0; c < nchunk; c++) {
        asm volatile("cp.async.wait_group %0;" :: "n"(STAGES - 2));
        __syncthreads();

        const int nc = c + STAGES - 1;
        if (nc < nchunk) load_stage(nc % STAGES, nc);
        asm volatile("cp.async.commit_group;");

        const uint32_t st = sb + (uint32_t)((c % STAGES) * STAGE_HALFS) * 2u;
        load_frags(st, 0, 0);
#pragma unroll
        for (int kk = 0; kk < BKH / 16; kk++) {
            const int cur = kk & 1;
            if (kk < BKH / 16 - 1) load_frags(st, kk + 1, cur ^ 1);
#pragma unroll
            for (int ms = 0; ms < 4; ms++)
#pragma unroll
                for (int ns = 0; ns < 8; ns++) mma16(acc[ms][ns], af[cur][ms], bf[cur][ns]);
        }
    }

    // epilogue
#pragma unroll
    for (int ms = 0; ms < 4; ms++) {
        const int r0 = bm + wm * 64 + ms * 16 + gq;
        const int r1 = r0 + 8;
        const float bv0 = BROW ? bias[r0] : 0.f;
        const float bv1 = BROW ? bias[r1] : 0.f;
#pragma unroll
        for (int ns = 0; ns < 8; ns++) {
            const int col = bn + wn * 64 + ns * 8 + tq * 2;
            float2 o0, o1;
            o0.x = alpha * acc[ms][ns][0] + bv0;
            o0.y = alpha * acc[ms][ns][1] + bv0;
            o1.x = alpha * acc[ms][ns][2] + bv1;
            o1.y = alpha * acc[ms][ns][3] + bv1;
            if (BCOL) {
                const float bc0 = bias[col], bc1 = bias[col + 1];
                o0.x += bc0; o0.y += bc1;
                o1.x += bc0; o1.y += bc1;
            }
            if (RES) {
                const float2 q0 = *reinterpret_cast<const float2*>(&res[(size_t)r0 * N + col]);
                const float2 q1 = *reinterpret_cast<const float2*>(&res[(size_t)r1 * N + col]);
                o0.x += q0.x; o0.y += q0.y;
                o1.x += q1.x; o1.y += q1.y;
            }
            if (OUTH) {
                *reinterpret_cast<__half2*>(&Ch[(size_t)r0 * N + col]) = __floats2half2_rn(o0.x, o0.y);
                *reinterpret_cast<__half2*>(&Ch[(size_t)r1 * N + col]) = __floats2half2_rn(o1.x, o1.y);
            } else {
                *reinterpret_cast<float2*>(&Cf[(size_t)r0 * N + col]) = o0;
                *reinterpret_cast<float2*>(&Cf[(size_t)r1 * N + col]) = o1;
            }
        }
    }
}

// ---------------------------------------------------------------------------
// convert the four weight matrices to fp16 in g_wh (order: qw, kw, vw, pw)
// ---------------------------------------------------------------------------
__global__ void __launch_bounds__(256) conv_w(const float* __restrict__ qw,
                                              const float* __restrict__ kw,
                                              const float* __restrict__ vw,
                                              const float* __restrict__ pw,
                                              __half* __restrict__ o) {
    const int i = blockIdx.x * 256 + threadIdx.x;  // C*C total
    o[i] = __float2half_rn(qw[i]);
    o[C * C + i] = __float2half_rn(kw[i]);
    o[2 * C * C + i] = __float2half_rn(vw[i]);
    o[3 * C * C + i] = __float2half_rn(pw[i]);
}

__global__ void qkb_kernel(const float* __restrict__ qb, const float* __restrict__ kb,
                           float* __restrict__ o) {
    const int i = threadIdx.x;  // 512
    o[i] = qb[i];
    o[C + i] = kb[i];
}

// ---------------------------------------------------------------------------
// GroupNorm -> transposed fp16 output hT [B, HW, C]
// ---------------------------------------------------------------------------
__global__ void __launch_bounds__(512) gn_kernel(const float* __restrict__ x,
                                                 const float* __restrict__ w,
                                                 const float* __restrict__ b,
                                                 __half* __restrict__ hT) {
    const int batch = blockIdx.x / G;
    const int g = blockIdx.x % G;
    const float* xp = x + ((size_t)batch * C + (size_t)g * CPG) * HW;

    float sum = 0.f, sq = 0.f;
    for (int i = threadIdx.x; i < CPG * HW; i += blockDim.x) {
        const float v = xp[i];
        sum += v; sq += v * v;
    }
    __shared__ float s1[32], s2[32];
#pragma unroll
    for (int o = 16; o; o >>= 1) {
        sum += __shfl_xor_sync(~0u, sum, o);
        sq += __shfl_xor_sync(~0u, sq, o);
    }
    const int lane = threadIdx.x & 31, wid = threadIdx.x >> 5;
    if (lane == 0) { s1[wid] = sum; s2[wid] = sq; }
    __syncthreads();
    if (wid == 0) {
        sum = lane < 16 ? s1[lane] : 0.f;
        sq = lane < 16 ? s2[lane] : 0.f;
#pragma unroll
        for (int o = 16; o; o >>= 1) {
            sum += __shfl_xor_sync(~0u, sum, o);
            sq += __shfl_xor_sync(~0u, sq, o);
        }
        if (lane == 0) {
            const float inv_n = 1.f / (float)(CPG * HW);
            const float m = sum * inv_n;
            const float var = sq * inv_n - m * m;
            s1[0] = m;
            s2[0] = rsqrtf(var + EPS);
        }
    }
    __syncthreads();
    const float m = s1[0], r = s2[0];

    float ws[CPG], bs[CPG];
#pragma unroll
    for (int j = 0; j < CPG; j++) {
        const float wj = w[g * CPG + j];
        ws[j] = wj * r;
        bs[j] = b[g * CPG + j] - m * wj * r;
    }
    for (int p = threadIdx.x; p < HW; p += blockDim.x) {
        __half2 o[CPG / 2];
#pragma unroll
        for (int j = 0; j < CPG; j += 2)
            o[j / 2] = __floats2half2_rn(xp[(size_t)j * HW + p] * ws[j] + bs[j],
                                         xp[(size_t)(j + 1) * HW + p] * ws[j + 1] + bs[j + 1]);
        __half2* dst = reinterpret_cast<__half2*>(hT + ((size_t)batch * HW + p) * C + g * CPG);
#pragma unroll
        for (int j = 0; j < CPG / 2; j++) dst[j] = o[j];
    }
}

// ---------------------------------------------------------------------------
// Row softmax over 4096 fp32 scores -> fp16 attn.
// ---------------------------------------------------------------------------
__global__ void __launch_bounds__(256) softmax_kernel(const float* __restrict__ s,
                                                      __half* __restrict__ at) {
    const float4* row = reinterpret_cast<const float4*>(s + (size_t)blockIdx.x * HW);
    uint2* orow = reinterpret_cast<uint2*>(at + (size_t)blockIdx.x * HW);
    const int t = threadIdx.x;
    float4 v[4];
    float mx = -1e30f;
#pragma unroll
    for (int i = 0; i < 4; i++) {
        v[i] = row[t + i * 256];
        mx = fmaxf(fmaxf(fmaxf(v[i].x, v[i].y), fmaxf(v[i].z, v[i].w)), mx);
    }
    __shared__ float shm[8], shs[8];
#pragma unroll
    for (int o = 16; o; o >>= 1) mx = fmaxf(mx, __shfl_xor_sync(~0u, mx, o));
    const int lane = t & 31, wid = t >> 5;
    if (lane == 0) shm[wid] = mx;
    __syncthreads();
    mx = shm[0];
#pragma unroll
    for (int i = 1; i < 8; i++) mx = fmaxf(mx, shm[i]);
    float sum = 0.f;
#pragma unroll
    for (int i = 0; i < 4; i++) {
        v[i].x = __expf(v[i].x - mx); v[i].y = __expf(v[i].y - mx);
        v[i].z = __expf(v[i].z - mx); v[i].w = __expf(v[i].w - mx);
        sum += (v[i].x + v[i].y) + (v[i].z + v[i].w);
    }
#pragma unroll
    for (int o = 16; o; o >>= 1) sum += __shfl_xor_sync(~0u, sum, o);
    if (lane == 0) shs[wid] = sum;
    __syncthreads();
    sum = 0.f;
#pragma unroll
    for (int i = 0; i < 8; i++) sum += shs[i];
    const float inv = 1.f / sum;
#pragma unroll
    for (int i = 0; i < 4; i++) {
        const __half2 h01 = __floats2half2_rn(v[i].x * inv, v[i].y * inv);
        const __half2 h23 = __floats2half2_rn(v[i].z * inv, v[i].w * inv);
        uint2 o;
        o.x = *reinterpret_cast<const uint32_t*>(&h01);
        o.y = *reinterpret_cast<const uint32_t*>(&h23);
        orow[t + i * 256] = o;
    }
}

// ---------------------------------------------------------------------------
extern "C" void kernel_launch(void* const* d_in, const int* in_sizes, int n_in,
                              void* d_out, int out_size) {
    const float* x   = (const float*)d_in[0];
    const float* gnw = (const float*)d_in[1];
    const float* gnb = (const float*)d_in[2];
    const float* qw  = (const float*)d_in[3];
    const float* qb  = (const float*)d_in[4];
    const float* kw  = (const float*)d_in[5];
    const float* kb  = (const float*)d_in[6];
    const float* vw  = (const float*)d_in[7];
    const float* vb  = (const float*)d_in[8];
    const float* pw  = (const float*)d_in[9];
    const float* pb  = (const float*)d_in[10];
    float* out = (float*)d_out;

    __half *hth, *qkth, *vh, *at, *oth, *wh;
    float *s, *qkb;
    cudaGetSymbolAddress((void**)&hth, g_hth);
    cudaGetSymbolAddress((void**)&qkth, g_qkth);
    cudaGetSymbolAddress((void**)&vh, g_vh);
    cudaGetSymbolAddress((void**)&s, g_s);
    cudaGetSymbolAddress((void**)&at, g_at);
    cudaGetSymbolAddress((void**)&oth, g_oth);
    cudaGetSymbolAddress((void**)&wh, g_wh);
    cudaGetSymbolAddress((void**)&qkb, g_qkb);

    cudaFuncSetAttribute(hgemm<false, true,  false, true >, cudaFuncAttributeMaxDynamicSharedMemorySize, SMEM_BYTES);
    cudaFuncSetAttribute(hgemm<true,  false, false, true >, cudaFuncAttributeMaxDynamicSharedMemorySize, SMEM_BYTES);
    cudaFuncSetAttribute(hgemm<false, false, false, false>, cudaFuncAttributeMaxDynamicSharedMemorySize, SMEM_BYTES);
    cudaFuncSetAttribute(hgemm<false, false, false, true >, cudaFuncAttributeMaxDynamicSharedMemorySize, SMEM_BYTES);
    cudaFuncSetAttribute(hgemm<true,  false, true,  false>, cudaFuncAttributeMaxDynamicSharedMemorySize, SMEM_BYTES);

    const size_t sHC = (size_t)HW * C;
    const size_t sQK = (size_t)HW * 2 * C;
    const size_t sS = (size_t)HW * HW;
    const float scale = 0.044194173824159216f;  // 512^-0.5

    // 0) fp16 weights + combined qk bias; 1) GroupNorm -> hT (fp16)
    conv_w<<<C * C / 256, 256>>>(qw, kw, vw, pw, wh);
    qkb_kernel<<<1, C>>>(qb, kb, qkb);
    gn_kernel<<<BATCH * G, 512>>>(x, gnw, gnb, hth);

    const __half* vwh = wh + (size_t)2 * C * C;
    const __half* pwh = wh + (size_t)3 * C * C;

    dim3 blk(256);
    // 2) [qT|kT] = hT @ [qw;kw]^T + bias(col):  M=HW, N=2C, K=C
    dim3 g1(2 * C / BN, HW / BM, BATCH);
    hgemm<false, true, false, true><<<g1, blk, SMEM_BYTES>>>(
        hth, wh, qkb, nullptr, qkth, HW, 2 * C, C, C, C, 1.f, sHC, 0, sQK, 0);
    //    v = W @ h + bias(row):  M=C, N=HW, K=C
    dim3 g2(HW / BN, C / BM, BATCH);
    hgemm<true, false, false, true><<<g2, blk, SMEM_BYTES>>>(
        vwh, hth, vb, nullptr, vh, C, HW, C, C, C, 1.f, 0, sHC, sHC, 0);

    // 3) scores = qT @ kT^T * scale (fp32 out):  M=HW, N=HW, K=C
    dim3 g3(HW / BN, HW / BM, BATCH);
    hgemm<false, false, false, false><<<g3, blk, SMEM_BYTES>>>(
        qkth, qkth + C, nullptr, nullptr, s, HW, HW, C, 2 * C, 2 * C, scale, sQK, sQK, sS, 0);

    // 4) softmax rows -> fp16 attn
    softmax_kernel<<<BATCH * HW, 256>>>(s, at);

    // 5) oT = attn @ v^T:  M=HW(q), N=C(d), K=HW(k)
    dim3 g5(C / BN, HW / BM, BATCH);
    hgemm<false, false, false, true><<<g5, blk, SMEM_BYTES>>>(
        at, vh, nullptr, nullptr, oth, HW, C, HW, HW, HW, 1.f, sS, sHC, sHC, 0);

    // 6) out = x + pw @ o + pb:  M=C, N=HW, K=C
    dim3 g6(HW / BN, C / BM, BATCH);
    hgemm<true, false, true, false><<<g6, blk, SMEM_BYTES>>>(
        pwh, oth, pb, x, out, C, HW, C, C, C, 1.f, 0, sHC, sHC, sHC);
}

// round 12
// speedup vs baseline: 1.9269x; 1.0063x over previous
#include <cuda_runtime.h>
#include <cuda_fp16.h>
#include <cstdint>
#include <math.h>

#define BATCH 4
#define C 512
#define HW 4096
#define G 32
#define CPG 16
#define EPS 1e-5f

// GEMM tiling (fp16 operands, fp32 accumulate)
#define BM 128
#define BN 256
#define BKH 64                                    // K halves per chunk (128 bytes)
#define STAGES 4
#define PADH 72                                   // halves per smem row (144B; stride 36 words -> conflict-free)
#define STAGE_HALFS ((BM + BN) * PADH)            // 27648
#define SMEM_BYTES (STAGES * STAGE_HALFS * 2)     // 221184

// Scratch (static device memory — no allocations)
__device__ __half g_hth [(size_t)BATCH * HW * C];      // groupnorm out^T [HW, C]
__device__ __half g_qkth[(size_t)BATCH * HW * 2 * C];  // q^T | k^T [HW, 2C]
__device__ __half g_vh  [(size_t)BATCH * C * HW];      // v [C, HW]
__device__ __half g_at  [(size_t)BATCH * HW * HW];     // scores -> attn fp16 [HWq, HWk]
__device__ __half g_oth [(size_t)BATCH * HW * C];      // attn out^T [HW, C]
__device__ __half g_wh  [(size_t)4 * C * C];           // fp16 weights: qw, kw, vw, pw
__device__ float  g_qkb[2 * C];                        // combined qb|kb

// ---------------------------------------------------------------------------
// helpers
// ---------------------------------------------------------------------------
__device__ __forceinline__ uint32_t smem_u32(const void* p) {
    uint32_t a;
    asm("{ .reg .u64 t; cvta.to.shared.u64 t, %1; cvt.u32.u64 %0, t; }" : "=r"(a) : "l"(p));
    return a;
}

__device__ __forceinline__ void cp16(uint32_t dst, const void* src) {
    asm volatile("cp.async.cg.shared.global [%0], [%1], 16;" :: "r"(dst), "l"(src));
}

__device__ __forceinline__ void mma16(float* c, const uint32_t* a, const uint32_t* b) {
    asm volatile(
        "mma.sync.aligned.m16n8k16.row.col.f32.f16.f16.f32 "
        "{%0,%1,%2,%3}, {%4,%5,%6,%7}, {%8,%9}, {%0,%1,%2,%3};"
        : "+f"(c[0]), "+f"(c[1]), "+f"(c[2]), "+f"(c[3])
        : "r"(a[0]), "r"(a[1]), "r"(a[2]), "r"(a[3]), "r"(b[0]), "r"(b[1]));
}

#define LDSM4(r0, r1, r2, r3, addr)                                             \
    asm volatile("ldmatrix.sync.aligned.m8n8.x4.shared.b16 {%0,%1,%2,%3}, [%4];" \
                 : "=r"(r0), "=r"(r1), "=r"(r2), "=r"(r3) : "r"(addr))

// ---------------------------------------------------------------------------
// fp16 mma.sync GEMM: D[m,n] = alpha * sum_k A[m,k]*B[n,k] (+bias) (+res)
// A: [M,K] half, rows stride ldA; B: [N,K] half, rows stride ldB.
// Out: [M,N] row-major, fp32 or fp16 (OUTH). Block tile 128x256, 256 threads
// (8 warps, 2x4 grid of 64x64 warp tiles), BKH=64, 4-stage cp.async pipeline,
// ldmatrix fragment loads, register double-buffered over k16 steps.
// M%128==0, N%256==0, K%64==0, K/64>=STAGES-1.
// ---------------------------------------------------------------------------
template <bool BROW, bool BCOL, bool RES, bool OUTH>
__global__ void __launch_bounds__(256, 1) hgemm(
    const __half* __restrict__ A, const __half* __restrict__ B,
    const float* __restrict__ bias, const float* __restrict__ res,
    void* __restrict__ CoutV, int M, int N, int K, int ldA, int ldB, float alpha,
    size_t sA, size_t sB, size_t sC, size_t sRes) {
    extern __shared__ __half smh[];
    const int tid = threadIdx.x;
    const int wid = tid >> 5, lane = tid & 31;
    const int wm = wid >> 2, wn = wid & 3;      // warp grid 2 (M) x 4 (N)
    const int gq = lane >> 2, tq = lane & 3;    // quad decomposition
    const int lj = lane >> 3, lr = lane & 7;    // ldmatrix matrix id / row
    const int bm = blockIdx.y * BM;
    const int bn = blockIdx.x * BN;

    A += (size_t)blockIdx.z * sA;
    B += (size_t)blockIdx.z * sB;
    float* Cf = (float*)CoutV + (size_t)blockIdx.z * sC;
    __half* Ch = (__half*)CoutV + (size_t)blockIdx.z * sC;
    if (RES) res += (size_t)blockIdx.z * sRes;

    const uint32_t sb = smem_u32(smh);

    // per-lane ldmatrix byte offsets within a stage
    const uint32_t a_lane = ((uint32_t)((wm * 64 + (lj & 1) * 8 + lr) * PADH + (lj >> 1) * 8)) * 2u;
    const uint32_t b_lane = ((uint32_t)((wn * 64 + (lj >> 1) * 8 + lr) * PADH + (lj & 1) * 8)) * 2u
                            + (uint32_t)(BM * PADH) * 2u;

    float acc[4][8][4];
#pragma unroll
    for (int i = 0; i < 4; i++)
#pragma unroll
        for (int j = 0; j < 8; j++)
#pragma unroll
            for (int l = 0; l < 4; l++) acc[i][j][l] = 0.f;

    const int nchunk = K / BKH;

    // stage loader: A 1024 cp16 + B 2048 cp16 over 256 threads (12 each)
    auto load_stage = [&](int s, int c) {
        const int k0 = c * BKH;
        const uint32_t st = sb + (uint32_t)(s * STAGE_HALFS) * 2u;
#pragma unroll
        for (int t = 0; t < 4; t++) {
            const int i = tid + t * 256;
            const int row = i >> 3, q = i & 7;
            cp16(st + (uint32_t)(row * PADH + q * 8) * 2u,
                 &A[(size_t)(bm + row) * ldA + k0 + q * 8]);
        }
        const uint32_t stB = st + (uint32_t)(BM * PADH) * 2u;
#pragma unroll
        for (int t = 0; t < 8; t++) {
            const int i = tid + t * 256;
            const int row = i >> 3, q = i & 7;
            cp16(stB + (uint32_t)(row * PADH + q * 8) * 2u,
                 &B[(size_t)(bn + row) * ldB + k0 + q * 8]);
        }
    };

    uint32_t af[2][4][4], bf[2][8][2];

    auto load_frags = [&](uint32_t st, int kk, int buf) {
        const uint32_t ka = st + a_lane + (uint32_t)(kk * 16) * 2u;
        const uint32_t kb = st + b_lane + (uint32_t)(kk * 16) * 2u;
#pragma unroll
        for (int ms = 0; ms < 4; ms++)
            LDSM4(af[buf][ms][0], af[buf][ms][1], af[buf][ms][2], af[buf][ms][3],
                  ka + (uint32_t)(ms * 16 * PADH) * 2u);
#pragma unroll
        for (int p = 0; p < 4; p++)
            LDSM4(bf[buf][2 * p][0], bf[buf][2 * p][1], bf[buf][2 * p + 1][0], bf[buf][2 * p + 1][1],
                  kb + (uint32_t)(p * 16 * PADH) * 2u);
    };

#pragma unroll
    for (int s = 0; s < STAGES - 1; s++) {
        load_stage(s, s);
        asm volatile("cp.async.commit_group;");
    }

    for (int c = 0; c < nchunk; c++) {
        asm volatile("cp.async.wait_group %0;" :: "n"(STAGES - 2));
        __syncthreads();

        const int nc = c + STAGES - 1;
        if (nc < nchunk) load_stage(nc % STAGES, nc);
        asm volatile("cp.async.commit_group;");

        const uint32_t st = sb + (uint32_t)((c % STAGES) * STAGE_HALFS) * 2u;
        load_frags(st, 0, 0);
#pragma unroll
        for (int kk = 0; kk < BKH / 16; kk++) {
            const int cur = kk & 1;
            if (kk < BKH / 16 - 1) load_frags(st, kk + 1, cur ^ 1);
#pragma unroll
            for (int ms = 0; ms < 4; ms++)
#pragma unroll
                for (int ns = 0; ns < 8; ns++) mma16(acc[ms][ns], af[cur][ms], bf[cur][ns]);
        }
    }

    // epilogue
#pragma unroll
    for (int ms = 0; ms < 4; ms++) {
        const int r0 = bm + wm * 64 + ms * 16 + gq;
        const int r1 = r0 + 8;
        const float bv0 = BROW ? bias[r0] : 0.f;
        const float bv1 = BROW ? bias[r1] : 0.f;
#pragma unroll
        for (int ns = 0; ns < 8; ns++) {
            const int col = bn + wn * 64 + ns * 8 + tq * 2;
            float2 o0, o1;
            o0.x = alpha * acc[ms][ns][0] + bv0;
            o0.y = alpha * acc[ms][ns][1] + bv0;
            o1.x = alpha * acc[ms][ns][2] + bv1;
            o1.y = alpha * acc[ms][ns][3] + bv1;
            if (BCOL) {
                const float bc0 = bias[col], bc1 = bias[col + 1];
                o0.x += bc0; o0.y += bc1;
                o1.x += bc0; o1.y += bc1;
            }
            if (RES) {
                const float2 q0 = *reinterpret_cast<const float2*>(&res[(size_t)r0 * N + col]);
                const float2 q1 = *reinterpret_cast<const float2*>(&res[(size_t)r1 * N + col]);
                o0.x += q0.x; o0.y += q0.y;
                o1.x += q1.x; o1.y += q1.y;
            }
            if (OUTH) {
                *reinterpret_cast<__half2*>(&Ch[(size_t)r0 * N + col]) = __floats2half2_rn(o0.x, o0.y);
                *reinterpret_cast<__half2*>(&Ch[(size_t)r1 * N + col]) = __floats2half2_rn(o1.x, o1.y);
            } else {
                *reinterpret_cast<float2*>(&Cf[(size_t)r0 * N + col]) = o0;
                *reinterpret_cast<float2*>(&Cf[(size_t)r1 * N + col]) = o1;
            }
        }
    }
}

// ---------------------------------------------------------------------------
// convert the four weight matrices to fp16 in g_wh (order: qw, kw, vw, pw)
// ---------------------------------------------------------------------------
__global__ void __launch_bounds__(256) conv_w(const float* __restrict__ qw,
                                              const float* __restrict__ kw,
                                              const float* __restrict__ vw,
                                              const float* __restrict__ pw,
                                              __half* __restrict__ o) {
    const int i = blockIdx.x * 256 + threadIdx.x;  // C*C total
    o[i] = __float2half_rn(qw[i]);
    o[C * C + i] = __float2half_rn(kw[i]);
    o[2 * C * C + i] = __float2half_rn(vw[i]);
    o[3 * C * C + i] = __float2half_rn(pw[i]);
}

__global__ void qkb_kernel(const float* __restrict__ qb, const float* __restrict__ kb,
                           float* __restrict__ o) {
    const int i = threadIdx.x;  // 512
    o[i] = qb[i];
    o[C + i] = kb[i];
}

// ---------------------------------------------------------------------------
// GroupNorm -> transposed fp16 output hT [B, HW, C]
// ---------------------------------------------------------------------------
__global__ void __launch_bounds__(512) gn_kernel(const float* __restrict__ x,
                                                 const float* __restrict__ w,
                                                 const float* __restrict__ b,
                                                 __half* __restrict__ hT) {
    const int batch = blockIdx.x / G;
    const int g = blockIdx.x % G;
    const float* xp = x + ((size_t)batch * C + (size_t)g * CPG) * HW;

    float sum = 0.f, sq = 0.f;
    for (int i = threadIdx.x; i < CPG * HW; i += blockDim.x) {
        const float v = xp[i];
        sum += v; sq += v * v;
    }
    __shared__ float s1[32], s2[32];
#pragma unroll
    for (int o = 16; o; o >>= 1) {
        sum += __shfl_xor_sync(~0u, sum, o);
        sq += __shfl_xor_sync(~0u, sq, o);
    }
    const int lane = threadIdx.x & 31, wid = threadIdx.x >> 5;
    if (lane == 0) { s1[wid] = sum; s2[wid] = sq; }
    __syncthreads();
    if (wid == 0) {
        sum = lane < 16 ? s1[lane] : 0.f;
        sq = lane < 16 ? s2[lane] : 0.f;
#pragma unroll
        for (int o = 16; o; o >>= 1) {
            sum += __shfl_xor_sync(~0u, sum, o);
            sq += __shfl_xor_sync(~0u, sq, o);
        }
        if (lane == 0) {
            const float inv_n = 1.f / (float)(CPG * HW);
            const float m = sum * inv_n;
            const float var = sq * inv_n - m * m;
            s1[0] = m;
            s2[0] = rsqrtf(var + EPS);
        }
    }
    __syncthreads();
    const float m = s1[0], r = s2[0];

    float ws[CPG], bs[CPG];
#pragma unroll
    for (int j = 0; j < CPG; j++) {
        const float wj = w[g * CPG + j];
        ws[j] = wj * r;
        bs[j] = b[g * CPG + j] - m * wj * r;
    }
    for (int p = threadIdx.x; p < HW; p += blockDim.x) {
        __half2 o[CPG / 2];
#pragma unroll
        for (int j = 0; j < CPG; j += 2)
            o[j / 2] = __floats2half2_rn(xp[(size_t)j * HW + p] * ws[j] + bs[j],
                                         xp[(size_t)(j + 1) * HW + p] * ws[j + 1] + bs[j + 1]);
        __half2* dst = reinterpret_cast<__half2*>(hT + ((size_t)batch * HW + p) * C + g * CPG);
#pragma unroll
        for (int j = 0; j < CPG / 2; j++) dst[j] = o[j];
    }
}

// ---------------------------------------------------------------------------
// Row softmax over 4096 fp16 scores, in place (fp32 math).
// ---------------------------------------------------------------------------
__global__ void __launch_bounds__(256) softmax_kernel(__half* __restrict__ at) {
    uint4* row = reinterpret_cast<uint4*>(at + (size_t)blockIdx.x * HW);  // 512 uint4 (8 halves each)
    const int t = threadIdx.x;
    uint4 u[2];
    u[0] = row[t];
    u[1] = row[t + 256];
    float v[16];
#pragma unroll
    for (int i = 0; i < 2; i++) {
        const __half2* h = reinterpret_cast<const __half2*>(&u[i]);
#pragma unroll
        for (int j = 0; j < 4; j++) {
            const float2 f = __half22float2(h[j]);
            v[i * 8 + j * 2] = f.x;
            v[i * 8 + j * 2 + 1] = f.y;
        }
    }
    float mx = -1e30f;
#pragma unroll
    for (int i = 0; i < 16; i++) mx = fmaxf(mx, v[i]);
    __shared__ float shm[8], shs[8];
#pragma unroll
    for (int o = 16; o; o >>= 1) mx = fmaxf(mx, __shfl_xor_sync(~0u, mx, o));
    const int lane = t & 31, wid = t >> 5;
    if (lane == 0) shm[wid] = mx;
    __syncthreads();
    mx = shm[0];
#pragma unroll
    for (int i = 1; i < 8; i++) mx = fmaxf(mx, shm[i]);
    float sum = 0.f;
#pragma unroll
    for (int i = 0; i < 16; i++) { v[i] = __expf(v[i] - mx); sum += v[i]; }
#pragma unroll
    for (int o = 16; o; o >>= 1) sum += __shfl_xor_sync(~0u, sum, o);
    if (lane == 0) shs[wid] = sum;
    __syncthreads();
    sum = 0.f;
#pragma unroll
    for (int i = 0; i < 8; i++) sum += shs[i];
    const float inv = 1.f / sum;
#pragma unroll
    for (int i = 0; i < 2; i++) {
        __half2* h = reinterpret_cast<__half2*>(&u[i]);
#pragma unroll
        for (int j = 0; j < 4; j++)
            h[j] = __floats2half2_rn(v[i * 8 + j * 2] * inv, v[i * 8 + j * 2 + 1] * inv);
    }
    row[t] = u[0];
    row[t + 256] = u[1];
}

// ---------------------------------------------------------------------------
extern "C" void kernel_launch(void* const* d_in, const int* in_sizes, int n_in,
                              void* d_out, int out_size) {
    const float* x   = (const float*)d_in[0];
    const float* gnw = (const float*)d_in[1];
    const float* gnb = (const float*)d_in[2];
    const float* qw  = (const float*)d_in[3];
    const float* qb  = (const float*)d_in[4];
    const float* kw  = (const float*)d_in[5];
    const float* kb  = (const float*)d_in[6];
    const float* vw  = (const float*)d_in[7];
    const float* vb  = (const float*)d_in[8];
    const float* pw  = (const float*)d_in[9];
    const float* pb  = (const float*)d_in[10];
    float* out = (float*)d_out;

    __half *hth, *qkth, *vh, *at, *oth, *wh;
    float *qkb;
    cudaGetSymbolAddress((void**)&hth, g_hth);
    cudaGetSymbolAddress((void**)&qkth, g_qkth);
    cudaGetSymbolAddress((void**)&vh, g_vh);
    cudaGetSymbolAddress((void**)&at, g_at);
    cudaGetSymbolAddress((void**)&oth, g_oth);
    cudaGetSymbolAddress((void**)&wh, g_wh);
    cudaGetSymbolAddress((void**)&qkb, g_qkb);

    cudaFuncSetAttribute(hgemm<false, true,  false, true >, cudaFuncAttributeMaxDynamicSharedMemorySize, SMEM_BYTES);
    cudaFuncSetAttribute(hgemm<true,  false, false, true >, cudaFuncAttributeMaxDynamicSharedMemorySize, SMEM_BYTES);
    cudaFuncSetAttribute(hgemm<false, false, false, true >, cudaFuncAttributeMaxDynamicSharedMemorySize, SMEM_BYTES);
    cudaFuncSetAttribute(hgemm<true,  false, true,  false>, cudaFuncAttributeMaxDynamicSharedMemorySize, SMEM_BYTES);

    const size_t sHC = (size_t)HW * C;
    const size_t sQK = (size_t)HW * 2 * C;
    const size_t sS = (size_t)HW * HW;
    const float scale = 0.044194173824159216f;  // 512^-0.5

    // 0) fp16 weights + combined qk bias; 1) GroupNorm -> hT (fp16)
    conv_w<<<C * C / 256, 256>>>(qw, kw, vw, pw, wh);
    qkb_kernel<<<1, C>>>(qb, kb, qkb);
    gn_kernel<<<BATCH * G, 512>>>(x, gnw, gnb, hth);

    const __half* vwh = wh + (size_t)2 * C * C;
    const __half* pwh = wh + (size_t)3 * C * C;

    dim3 blk(256);
    // 2) [qT|kT] = hT @ [qw;kw]^T + bias(col):  M=HW, N=2C, K=C
    dim3 g1(2 * C / BN, HW / BM, BATCH);
    hgemm<false, true, false, true><<<g1, blk, SMEM_BYTES>>>(
        hth, wh, qkb, nullptr, qkth, HW, 2 * C, C, C, C, 1.f, sHC, 0, sQK, 0);
    //    v = W @ h + bias(row):  M=C, N=HW, K=C
    dim3 g2(HW / BN, C / BM, BATCH);
    hgemm<true, false, false, true><<<g2, blk, SMEM_BYTES>>>(
        vwh, hth, vb, nullptr, vh, C, HW, C, C, C, 1.f, 0, sHC, sHC, 0);

    // 3) scores = qT @ kT^T * scale -> fp16 directly:  M=HW, N=HW, K=C
    dim3 g3(HW / BN, HW / BM, BATCH);
    hgemm<false, false, false, true><<<g3, blk, SMEM_BYTES>>>(
        qkth, qkth + C, nullptr, nullptr, at, HW, HW, C, 2 * C, 2 * C, scale, sQK, sQK, sS, 0);

    // 4) softmax rows in place (fp16)
    softmax_kernel<<<BATCH * HW, 256>>>(at);

    // 5) oT = attn @ v^T:  M=HW(q), N=C(d), K=HW(k)
    dim3 g5(C / BN, HW / BM, BATCH);
    hgemm<false, false, false, true><<<g5, blk, SMEM_BYTES>>>(
        at, vh, nullptr, nullptr, oth, HW, C, HW, HW, HW, 1.f, sS, sHC, sHC, 0);

    // 6) out = x + pw @ o + pb:  M=C, N=HW, K=C
    dim3 g6(HW / BN, C / BM, BATCH);
    hgemm<true, false, true, false><<<g6, blk, SMEM_BYTES>>>(
        pwh, oth, pb, x, out, C, HW, C, C, C, 1.f, 0, sHC, sHC, sHC);
}

// round 14
// speedup vs baseline: 2.3985x; 1.2448x over previous
#include <cuda_runtime.h>
#include <cuda_fp16.h>
#include <cstdint>
#include <math.h>

#define BATCH 4
#define C 512
#define HW 4096
#define G 32
#define CPG 16
#define EPS 1e-5f

// GEMM tiling (fp16 operands, fp32 accumulate)
#define BM 128
#define BN 256
#define BKH 64                               // K halves per chunk
#define STAGES 4
#define TILE_B 8192                          // 64x64 halves, swizzled
#define CHUNK_B (6 * TILE_B)                 // 2 A tiles + 4 B tiles = 49152
#define SMEM_BYTES (128 + STAGES * CHUNK_B)  // 196736

// Scratch (static device memory — no allocations). All half buffers below are
// stored TILED: [R/64, K/64] grid of 64x64-half tiles, each tile SW128-swizzled.
__device__ __half g_hth[(size_t)BATCH * HW * C];   // groupnorm out^T [HW, C]
__device__ __half g_qt [(size_t)BATCH * HW * C];   // q^T [HW, C]
__device__ __half g_kt [(size_t)BATCH * HW * C];   // k^T [HW, C]
__device__ __half g_vh [(size_t)BATCH * C * HW];   // v [C, HW]
__device__ __half g_at [(size_t)BATCH * HW * HW];  // scores -> attn [HWq, HWk]
__device__ __half g_oth[(size_t)BATCH * HW * C];   // attn out^T [HW, C]
__device__ __half g_qkw[(size_t)2 * C * C];        // combined qw|kw [2C, C]
__device__ __half g_vwt[(size_t)C * C];            // vw tiled
__device__ __half g_pwt[(size_t)C * C];            // pw tiled
__device__ float  g_qkb[2 * C];                    // combined qb|kb

// ---------------------------------------------------------------------------
// helpers
// ---------------------------------------------------------------------------
__device__ __forceinline__ uint32_t smem_u32(const void* p) {
    uint32_t a;
    asm("{ .reg .u64 t; cvta.to.shared.u64 t, %1; cvt.u32.u64 %0, t; }" : "=r"(a) : "l"(p));
    return a;
}

// byte offset of element (r, k) in a tiled buffer with Kt tiles per row-block
__device__ __forceinline__ uint32_t toff(int r, int k, int Kt) {
    uint32_t inner = ((uint32_t)(r & 63) << 7) + ((uint32_t)(k & 63) << 1);
    inner ^= (inner >> 3) & 0x70;
    return (((uint32_t)((r >> 6) * Kt + (k >> 6))) << 13) + inner;
}

__device__ __forceinline__ void mma16(float* c, const uint32_t* a, const uint32_t* b) {
    asm volatile(
        "mma.sync.aligned.m16n8k16.row.col.f32.f16.f16.f32 "
        "{%0,%1,%2,%3}, {%4,%5,%6,%7}, {%8,%9}, {%0,%1,%2,%3};"
        : "+f"(c[0]), "+f"(c[1]), "+f"(c[2]), "+f"(c[3])
        : "r"(a[0]), "r"(a[1]), "r"(a[2]), "r"(a[3]), "r"(b[0]), "r"(b[1]));
}

#define LDSM4(r0, r1, r2, r3, addr)                                             \
    asm volatile("ldmatrix.sync.aligned.m8n8.x4.shared.b16 {%0,%1,%2,%3}, [%4];" \
                 : "=r"(r0), "=r"(r1), "=r"(r2), "=r"(r3) : "r"(addr))

#define MBARRIER_INIT(addr, cnt) \
    asm volatile("mbarrier.init.shared.b64 [%0], %1;" :: "r"(addr), "r"(cnt) : "memory")

#define MBARRIER_EXPECT_TX(addr, tx) \
    asm volatile("mbarrier.arrive.expect_tx.shared.b64 _, [%0], %1;" :: "r"(addr), "r"(tx) : "memory")

#define MBARRIER_WAIT_PARITY(addr, par) do {                                          \
    uint32_t _m = (addr), _p = (par), _done;                                          \
    asm volatile("{\n\t.reg .pred p;\n\t"                                             \
        "mbarrier.try_wait.parity.acquire.cta.shared::cta.b64 p, [%1], %2;\n\t"       \
        "selp.b32 %0, 1, 0, p;\n\t}" : "=r"(_done) : "r"(_m), "r"(_p) : "memory");    \
    if (!_done) {                                                                     \
        asm volatile("{\n\t.reg .pred P1;\n\t"                                        \
            "WL_%=:\n\t"                                                              \
            "mbarrier.try_wait.parity.acquire.cta.shared::cta.b64 P1, [%0], %1, 0x989680;\n\t" \
            "@P1 bra.uni WD_%=;\n\t"                                                  \
            "bra.uni WL_%=;\n\t"                                                      \
            "WD_%=:\n\t}" :: "r"(_m), "r"(_p) : "memory");                            \
    }                                                                                 \
} while (0)

#define BULK_G2S(dst, src, bytes, mbar)                                                        \
    asm volatile("cp.async.bulk.shared::cluster.global.mbarrier::complete_tx::bytes "          \
                 "[%0], [%1], %2, [%3];"                                                       \
                 :: "r"(dst), "l"(src), "r"(bytes), "r"(mbar) : "memory")

// ---------------------------------------------------------------------------
// fp16 mma.sync GEMM on TILED operands: D[m,n] = alpha*sum_k A[m,k]*B[n,k] (+bias)(+res)
// A: [M,K] tiled (KtA tiles/row-block); B: [N,K] tiled (KtB). Block tile 128x256,
// 256 threads (8 warps, 2x4 of 64x64 warp tiles), chunk fill via cp.async.bulk
// (6x8KB per chunk) + mbarrier, 4-stage. ldmatrix frag loads, reg double-buffer.
// OUTM: 0 = fp32 plain row-major (+res); 1 = half tiled (KtO); 2 = half tiled
// split q|k (cols < 512 -> out0, else out1).
// M%128==0, N%256==0, K%64==0, K/64 >= STAGES-1.
// ---------------------------------------------------------------------------
template <int OUTM, bool BROW, bool BCOL, bool RES>
__global__ void __launch_bounds__(256, 1) hgemm(
    const __half* __restrict__ A, const __half* __restrict__ B,
    const float* __restrict__ bias, const float* __restrict__ res,
    void* __restrict__ out0, void* __restrict__ out1,
    int M, int N, int K, int KtA, int KtB, int KtO, float alpha,
    size_t sA, size_t sB, size_t sC, size_t sRes) {
    extern __shared__ __half smh[];
    const int tid = threadIdx.x;
    const int wid = tid >> 5, lane = tid & 31;
    const int wm = wid >> 2, wn = wid & 3;      // warp grid 2 (M) x 4 (N)
    const int gq = lane >> 2, tq = lane & 3;    // quad decomposition
    const int lj = lane >> 3, lr = lane & 7;    // ldmatrix matrix id / row
    const int bm = blockIdx.y * BM;
    const int bn = blockIdx.x * BN;
    const int z = blockIdx.z;

    const char* Ab = (const char*)(A + (size_t)z * sA);
    const char* Bb = (const char*)(B + (size_t)z * sB);
    if (RES) res += (size_t)z * sRes;

    const uint32_t sb = smem_u32(smh);
    const int bmt = bm >> 6, bnt = bn >> 6;
    const int nchunk = K / BKH;

    // lane constants for ldmatrix addressing (within 64x64 swizzled tiles)
    const int arow = (lj & 1) * 8 + lr;
    const uint32_t acolb = (uint32_t)((lj >> 1) * 16);
    const int brow = (lj >> 1) * 8 + lr;
    const uint32_t bcolb = (uint32_t)((lj & 1) * 16);

    // one-thread chunk issue: 2 A tiles + 4 B tiles, 8KB bulk each
    auto issue = [&](int s, int c) {
        const uint32_t mb = sb + s * 8;
        MBARRIER_EXPECT_TX(mb, (uint32_t)CHUNK_B);
        const uint32_t dst = sb + 128 + s * CHUNK_B;
#pragma unroll
        for (int i = 0; i < 2; i++)
            BULK_G2S(dst + i * TILE_B, Ab + ((size_t)(bmt + i) * KtA + c) * TILE_B,
                     (uint32_t)TILE_B, mb);
#pragma unroll
        for (int j = 0; j < 4; j++)
            BULK_G2S(dst + 2 * TILE_B + j * TILE_B, Bb + ((size_t)(bnt + j) * KtB + c) * TILE_B,
                     (uint32_t)TILE_B, mb);
    };

    if (tid == 0) {
#pragma unroll
        for (int s = 0; s < STAGES; s++) MBARRIER_INIT(sb + s * 8, 1);
        asm volatile("fence.proxy.async.shared::cta;" ::: "memory");
    }
    __syncthreads();
    if (tid == 0) {
        for (int s = 0; s < STAGES - 1 && s < nchunk; s++) issue(s, s);
    }

    float acc[4][8][4];
#pragma unroll
    for (int i = 0; i < 4; i++)
#pragma unroll
        for (int j = 0; j < 8; j++)
#pragma unroll
            for (int l = 0; l < 4; l++) acc[i][j][l] = 0.f;

    uint32_t af[2][4][4], bf[2][8][2];

    auto load_frags = [&](uint32_t sstage, int kk, int buf) {
        const uint32_t kkc = (uint32_t)(kk * 32);
        const uint32_t stA = sstage + ((uint32_t)wm << 13);
        const uint32_t stB = sstage + 2 * TILE_B + ((uint32_t)wn << 13);
#pragma unroll
        for (int ms = 0; ms < 4; ms++) {
            const int mrow = ms * 16 + arow;
            const uint32_t ad = stA + ((uint32_t)mrow << 7)
                                + ((kkc + acolb) ^ ((uint32_t)(mrow & 7) << 4));
            LDSM4(af[buf][ms][0], af[buf][ms][1], af[buf][ms][2], af[buf][ms][3], ad);
        }
#pragma unroll
        for (int p = 0; p < 4; p++) {
            const int nrow = p * 16 + brow;
            const uint32_t bd = stB + ((uint32_t)nrow << 7)
                                + ((kkc + bcolb) ^ ((uint32_t)(nrow & 7) << 4));
            LDSM4(bf[buf][2 * p][0], bf[buf][2 * p][1],
                  bf[buf][2 * p + 1][0], bf[buf][2 * p + 1][1], bd);
        }
    };

    for (int c = 0; c < nchunk; c++) {
        MBARRIER_WAIT_PARITY(sb + (c & 3) * 8, (c >> 2) & 1);
        __syncthreads();
        if (tid == 0 && c + STAGES - 1 < nchunk) issue((c + STAGES - 1) & 3, c + STAGES - 1);

        const uint32_t sstage = sb + 128 + (c & 3) * CHUNK_B;
        load_frags(sstage, 0, 0);
#pragma unroll
        for (int kk = 0; kk < 4; kk++) {
            const int cur = kk & 1;
            if (kk < 3) load_frags(sstage, kk + 1, cur ^ 1);
#pragma unroll
            for (int ms = 0; ms < 4; ms++)
#pragma unroll
                for (int ns = 0; ns < 8; ns++) mma16(acc[ms][ns], af[cur][ms], bf[cur][ns]);
        }
    }

    // epilogue
    float* Cf = (float*)out0 + (size_t)z * sC;
    char* C0 = (char*)((__half*)out0 + (size_t)z * sC);
    char* C1 = (OUTM == 2) ? (char*)((__half*)out1 + (size_t)z * sC) : nullptr;

#pragma unroll
    for (int ms = 0; ms < 4; ms++) {
        const int r0 = bm + wm * 64 + ms * 16 + gq;
        const int r1 = r0 + 8;
        const float bv0 = BROW ? bias[r0] : 0.f;
        const float bv1 = BROW ? bias[r1] : 0.f;
#pragma unroll
        for (int ns = 0; ns < 8; ns++) {
            const int col = bn + wn * 64 + ns * 8 + tq * 2;
            float2 o0, o1;
            o0.x = alpha * acc[ms][ns][0] + bv0;
            o0.y = alpha * acc[ms][ns][1] + bv0;
            o1.x = alpha * acc[ms][ns][2] + bv1;
            o1.y = alpha * acc[ms][ns][3] + bv1;
            if (BCOL) {
                const float bc0 = bias[col], bc1 = bias[col + 1];
                o0.x += bc0; o0.y += bc1;
                o1.x += bc0; o1.y += bc1;
            }
            if (RES) {
                const float2 q0 = *reinterpret_cast<const float2*>(&res[(size_t)r0 * N + col]);
                const float2 q1 = *reinterpret_cast<const float2*>(&res[(size_t)r1 * N + col]);
                o0.x += q0.x; o0.y += q0.y;
                o1.x += q1.x; o1.y += q1.y;
            }
            if (OUTM == 0) {
                *reinterpret_cast<float2*>(&Cf[(size_t)r0 * N + col]) = o0;
                *reinterpret_cast<float2*>(&Cf[(size_t)r1 * N + col]) = o1;
            } else if (OUTM == 1) {
                const __half2 h0 = __floats2half2_rn(o0.x, o0.y);
                const __half2 h1 = __floats2half2_rn(o1.x, o1.y);
                *reinterpret_cast<uint32_t*>(C0 + toff(r0, col, KtO)) = *(const uint32_t*)&h0;
                *reinterpret_cast<uint32_t*>(C0 + toff(r1, col, KtO)) = *(const uint32_t*)&h1;
            } else {
                char* dst = (col < C) ? C0 : C1;
                const int k = (col < C) ? col : col - C;
                const __half2 h0 = __floats2half2_rn(o0.x, o0.y);
                const __half2 h1 = __floats2half2_rn(o1.x, o1.y);
                *reinterpret_cast<uint32_t*>(dst + toff(r0, k, KtO)) = *(const uint32_t*)&h0;
                *reinterpret_cast<uint32_t*>(dst + toff(r1, k, KtO)) = *(const uint32_t*)&h1;
            }
        }
    }
}

// ---------------------------------------------------------------------------
// weights -> fp16 tiled: combined [qw;kw] (2C x C), vw, pw (C x C)
// ---------------------------------------------------------------------------
__global__ void __launch_bounds__(256) conv_w(const float* __restrict__ qw,
                                              const float* __restrict__ kw,
                                              const float* __restrict__ vw,
                                              const float* __restrict__ pw,
                                              __half* __restrict__ qkw,
                                              __half* __restrict__ vwt,
                                              __half* __restrict__ pwt) {
    const int u = blockIdx.x * 256 + threadIdx.x;  // 131072 units of 8 halves
    const float* src;
    char* dstb;
    int r, c;
    if (u < 65536) {
        r = u >> 6; c = (u & 63) * 8;
        src = (r < C) ? (qw + (size_t)r * C + c) : (kw + (size_t)(r - C) * C + c);
        dstb = (char*)qkw;
    } else if (u < 98304) {
        const int v = u - 65536;
        r = v >> 6; c = (v & 63) * 8;
        src = vw + (size_t)r * C + c;
        dstb = (char*)vwt;
    } else {
        const int v = u - 98304;
        r = v >> 6; c = (v & 63) * 8;
        src = pw + (size_t)r * C + c;
        dstb = (char*)pwt;
    }
    const float4 f0 = *reinterpret_cast<const float4*>(src);
    const float4 f1 = *reinterpret_cast<const float4*>(src + 4);
    __half2 h[4];
    h[0] = __floats2half2_rn(f0.x, f0.y);
    h[1] = __floats2half2_rn(f0.z, f0.w);
    h[2] = __floats2half2_rn(f1.x, f1.y);
    h[3] = __floats2half2_rn(f1.z, f1.w);
    *reinterpret_cast<uint4*>(dstb + toff(r, c, 8)) = *reinterpret_cast<const uint4*>(h);
}

__global__ void qkb_kernel(const float* __restrict__ qb, const float* __restrict__ kb,
                           float* __restrict__ o) {
    const int i = threadIdx.x;  // 512
    o[i] = qb[i];
    o[C + i] = kb[i];
}

// ---------------------------------------------------------------------------
// GroupNorm -> tiled fp16 hT [HW, C]
// ---------------------------------------------------------------------------
__global__ void __launch_bounds__(512) gn_kernel(const float* __restrict__ x,
                                                 const float* __restrict__ w,
                                                 const float* __restrict__ b,
                                                 __half* __restrict__ hT) {
    const int batch = blockIdx.x / G;
    const int g = blockIdx.x % G;
    const float* xp = x + ((size_t)batch * C + (size_t)g * CPG) * HW;
    char* dstb = (char*)(hT + (size_t)batch * HW * C);

    float sum = 0.f, sq = 0.f;
    for (int i = threadIdx.x; i < CPG * HW; i += blockDim.x) {
        const float v = xp[i];
        sum += v; sq += v * v;
    }
    __shared__ float s1[32], s2[32];
#pragma unroll
    for (int o = 16; o; o >>= 1) {
        sum += __shfl_xor_sync(~0u, sum, o);
        sq += __shfl_xor_sync(~0u, sq, o);
    }
    const int lane = threadIdx.x & 31, wid = threadIdx.x >> 5;
    if (lane == 0) { s1[wid] = sum; s2[wid] = sq; }
    __syncthreads();
    if (wid == 0) {
        sum = lane < 16 ? s1[lane] : 0.f;
        sq = lane < 16 ? s2[lane] : 0.f;
#pragma unroll
        for (int o = 16; o; o >>= 1) {
            sum += __shfl_xor_sync(~0u, sum, o);
            sq += __shfl_xor_sync(~0u, sq, o);
        }
        if (lane == 0) {
            const float inv_n = 1.f / (float)(CPG * HW);
            const float m = sum * inv_n;
            const float var = sq * inv_n - m * m;
            s1[0] = m;
            s2[0] = rsqrtf(var + EPS);
        }
    }
    __syncthreads();
    const float m = s1[0], r = s2[0];

    float ws[CPG], bs[CPG];
#pragma unroll
    for (int j = 0; j < CPG; j++) {
        const float wj = w[g * CPG + j];
        ws[j] = wj * r;
        bs[j] = b[g * CPG + j] - m * wj * r;
    }
    for (int p = threadIdx.x; p < HW; p += blockDim.x) {
        __half2 o[CPG / 2];
#pragma unroll
        for (int j = 0; j < CPG; j += 2)
            o[j / 2] = __floats2half2_rn(xp[(size_t)j * HW + p] * ws[j] + bs[j],
                                         xp[(size_t)(j + 1) * HW + p] * ws[j + 1] + bs[j + 1]);
        *reinterpret_cast<uint4*>(dstb + toff(p, g * CPG, 8)) =
            *reinterpret_cast<const uint4*>(&o[0]);
        *reinterpret_cast<uint4*>(dstb + toff(p, g * CPG + 8, 8)) =
            *reinterpret_cast<const uint4*>(&o[4]);
    }
}

// ---------------------------------------------------------------------------
// Row softmax over 4096 fp16 scores in TILED layout, in place (fp32 math).
// ---------------------------------------------------------------------------
__global__ void __launch_bounds__(256) softmax_kernel(__half* __restrict__ at) {
    const int b = blockIdx.x / HW;
    const int r = blockIdx.x % HW;
    char* base = (char*)(at + (size_t)b * HW * HW);
    const uint32_t rowblk = (uint32_t)(r >> 6) * 64;
    uint32_t inner = ((uint32_t)(r & 63) << 7);
    const int t = threadIdx.x;

    uint32_t offs[2];
    uint4 u[2];
#pragma unroll
    for (int i = 0; i < 2; i++) {
        const int un = t + i * 256;                 // unit 0..511
        const uint32_t in16 = inner + (uint32_t)(un & 7) * 16;
        offs[i] = ((rowblk + (uint32_t)(un >> 3)) << 13) + (in16 ^ ((in16 >> 3) & 0x70));
        u[i] = *reinterpret_cast<const uint4*>(base + offs[i]);
    }
    float v[16];
#pragma unroll
    for (int i = 0; i < 2; i++) {
        const __half2* h = reinterpret_cast<const __half2*>(&u[i]);
#pragma unroll
        for (int j = 0; j < 4; j++) {
            const float2 f = __half22float2(h[j]);
            v[i * 8 + j * 2] = f.x;
            v[i * 8 + j * 2 + 1] = f.y;
        }
    }
    float mx = -1e30f;
#pragma unroll
    for (int i = 0; i < 16; i++) mx = fmaxf(mx, v[i]);
    __shared__ float shm[8], shs[8];
#pragma unroll
    for (int o = 16; o; o >>= 1) mx = fmaxf(mx, __shfl_xor_sync(~0u, mx, o));
    const int lane = t & 31, wid = t >> 5;
    if (lane == 0) shm[wid] = mx;
    __syncthreads();
    mx = shm[0];
#pragma unroll
    for (int i = 1; i < 8; i++) mx = fmaxf(mx, shm[i]);
    float sum = 0.f;
#pragma unroll
    for (int i = 0; i < 16; i++) { v[i] = __expf(v[i] - mx); sum += v[i]; }
#pragma unroll
    for (int o = 16; o; o >>= 1) sum += __shfl_xor_sync(~0u, sum, o);
    if (lane == 0) shs[wid] = sum;
    __syncthreads();
    sum = 0.f;
#pragma unroll
    for (int i = 0; i < 8; i++) sum += shs[i];
    const float inv = 1.f / sum;
#pragma unroll
    for (int i = 0; i < 2; i++) {
        __half2* h = reinterpret_cast<__half2*>(&u[i]);
#pragma unroll
        for (int j = 0; j < 4; j++)
            h[j] = __floats2half2_rn(v[i * 8 + j * 2] * inv, v[i * 8 + j * 2 + 1] * inv);
        *reinterpret_cast<uint4*>(base + offs[i]) = u[i];
    }
}

// ---------------------------------------------------------------------------
extern "C" void kernel_launch(void* const* d_in, const int* in_sizes, int n_in,
                              void* d_out, int out_size) {
    const float* x   = (const float*)d_in[0];
    const float* gnw = (const float*)d_in[1];
    const float* gnb = (const float*)d_in[2];
    const float* qw  = (const float*)d_in[3];
    const float* qb  = (const float*)d_in[4];
    const float* kw  = (const float*)d_in[5];
    const float* kb  = (const float*)d_in[6];
    const float* vw  = (const float*)d_in[7];
    const float* vb  = (const float*)d_in[8];
    const float* pw  = (const float*)d_in[9];
    const float* pb  = (const float*)d_in[10];
    float* out = (float*)d_out;

    __half *hth, *qt, *kt, *vh, *at, *oth, *qkw, *vwt, *pwt;
    float *qkb;
    cudaGetSymbolAddress((void**)&hth, g_hth);
    cudaGetSymbolAddress((void**)&qt, g_qt);
    cudaGetSymbolAddress((void**)&kt, g_kt);
    cudaGetSymbolAddress((void**)&vh, g_vh);
    cudaGetSymbolAddress((void**)&at, g_at);
    cudaGetSymbolAddress((void**)&oth, g_oth);
    cudaGetSymbolAddress((void**)&qkw, g_qkw);
    cudaGetSymbolAddress((void**)&vwt, g_vwt);
    cudaGetSymbolAddress((void**)&pwt, g_pwt);
    cudaGetSymbolAddress((void**)&qkb, g_qkb);

    cudaFuncSetAttribute(hgemm<2, false, true,  false>, cudaFuncAttributeMaxDynamicSharedMemorySize, SMEM_BYTES);
    cudaFuncSetAttribute(hgemm<1, true,  false, false>, cudaFuncAttributeMaxDynamicSharedMemorySize, SMEM_BYTES);
    cudaFuncSetAttribute(hgemm<1, false, false, false>, cudaFuncAttributeMaxDynamicSharedMemorySize, SMEM_BYTES);
    cudaFuncSetAttribute(hgemm<0, true,  false, true >, cudaFuncAttributeMaxDynamicSharedMemorySize, SMEM_BYTES);

    const size_t sHC = (size_t)HW * C;
    const size_t sS = (size_t)HW * HW;
    const float scale = 0.044194173824159216f;  // 512^-0.5

    // 0) tiled fp16 weights + combined qk bias; 1) GroupNorm -> tiled hT
    conv_w<<<512, 256>>>(qw, kw, vw, pw, qkw, vwt, pwt);
    qkb_kernel<<<1, C>>>(qb, kb, qkb);
    gn_kernel<<<BATCH * G, 512>>>(x, gnw, gnb, hth);

    dim3 blk(256);
    // 2) [q|k] = hT @ [qw;kw]^T + bias(col):  M=HW, N=2C, K=C -> qt, kt tiled
    dim3 g1(2 * C / BN, HW / BM, BATCH);
    hgemm<2, false, true, false><<<g1, blk, SMEM_BYTES>>>(
        hth, qkw, qkb, nullptr, qt, kt, HW, 2 * C, C, 8, 8, 8, 1.f, sHC, 0, sHC, 0);
    //    v = vw @ h + bias(row):  M=C, N=HW, K=C -> vh tiled
    dim3 g2(HW / BN, C / BM, BATCH);
    hgemm<1, true, false, false><<<g2, blk, SMEM_BYTES>>>(
        vwt, hth, vb, nullptr, vh, nullptr, C, HW, C, 8, 8, 64, 1.f, 0, sHC, sHC, 0);

    // 3) scores = q @ k^T * scale:  M=HW, N=HW, K=C -> at tiled
    dim3 g3(HW / BN, HW / BM, BATCH);
    hgemm<1, false, false, false><<<g3, blk, SMEM_BYTES>>>(
        qt, kt, nullptr, nullptr, at, nullptr, HW, HW, C, 8, 8, 64, scale, sHC, sHC, sS, 0);

    // 4) softmax rows in place (tiled fp16)
    softmax_kernel<<<BATCH * HW, 256>>>(at);

    // 5) oT = attn @ v^T:  M=HW, N=C, K=HW -> oth tiled
    dim3 g5(C / BN, HW / BM, BATCH);
    hgemm<1, false, false, false><<<g5, blk, SMEM_BYTES>>>(
        at, vh, nullptr, nullptr, oth, nullptr, HW, C, HW, 64, 64, 8, 1.f, sS, sHC, sHC, 0);

    // 6) out = x + pw @ o + pb:  M=C, N=HW, K=C (fp32 plain out)
    dim3 g6(HW / BN, C / BM, BATCH);
    hgemm<0, true, false, true><<<g6, blk, SMEM_BYTES>>>(
        pwt, oth, pb, x, out, nullptr, C, HW, C, 8, 8, 0, 1.f, 0, sHC, sHC, sHC);
}

// round 15
// speedup vs baseline: 2.5514x; 1.0637x over previous
#include <cuda_runtime.h>
#include <cuda_fp16.h>
#include <cstdint>
#include <math.h>

#define BATCH 4
#define C 512
#define HW 4096
#define G 32
#define CPG 16
#define EPS 1e-5f

// GEMM tiling (fp16 operands, fp32 accumulate)
#define BM 128
#define BN 128
#define BKH 64                               // K halves per chunk
#define STAGES 3
#define TILE_B 8192                          // 64x64 halves, swizzled
#define CHUNK_B (4 * TILE_B)                 // 2 A tiles + 2 B tiles = 32768
#define SMEM_BYTES (128 + STAGES * CHUNK_B)  // 98432  (2 CTAs/SM fit)

// Scratch (static device memory — no allocations). All half buffers below are
// stored TILED: [R/64, K/64] grid of 64x64-half tiles, each tile SW128-swizzled.
__device__ __half g_hth[(size_t)BATCH * HW * C];   // groupnorm out^T [HW, C]
__device__ __half g_qt [(size_t)BATCH * HW * C];   // q^T [HW, C]
__device__ __half g_kt [(size_t)BATCH * HW * C];   // k^T [HW, C]
__device__ __half g_vh [(size_t)BATCH * C * HW];   // v [C, HW]
__device__ __half g_at [(size_t)BATCH * HW * HW];  // scores -> attn [HWq, HWk]
__device__ __half g_oth[(size_t)BATCH * HW * C];   // attn out^T [HW, C]
__device__ __half g_qkw[(size_t)2 * C * C];        // combined qw|kw [2C, C]
__device__ __half g_vwt[(size_t)C * C];            // vw tiled
__device__ __half g_pwt[(size_t)C * C];            // pw tiled
__device__ float  g_qkb[2 * C];                    // combined qb|kb

// ---------------------------------------------------------------------------
// helpers
// ---------------------------------------------------------------------------
__device__ __forceinline__ uint32_t smem_u32(const void* p) {
    uint32_t a;
    asm("{ .reg .u64 t; cvta.to.shared.u64 t, %1; cvt.u32.u64 %0, t; }" : "=r"(a) : "l"(p));
    return a;
}

// byte offset of element (r, k) in a tiled buffer with Kt tiles per row-block
__device__ __forceinline__ uint32_t toff(int r, int k, int Kt) {
    uint32_t inner = ((uint32_t)(r & 63) << 7) + ((uint32_t)(k & 63) << 1);
    inner ^= (inner >> 3) & 0x70;
    return (((uint32_t)((r >> 6) * Kt + (k >> 6))) << 13) + inner;
}

__device__ __forceinline__ void mma16(float* c, const uint32_t* a, const uint32_t* b) {
    asm volatile(
        "mma.sync.aligned.m16n8k16.row.col.f32.f16.f16.f32 "
        "{%0,%1,%2,%3}, {%4,%5,%6,%7}, {%8,%9}, {%0,%1,%2,%3};"
        : "+f"(c[0]), "+f"(c[1]), "+f"(c[2]), "+f"(c[3])
        : "r"(a[0]), "r"(a[1]), "r"(a[2]), "r"(a[3]), "r"(b[0]), "r"(b[1]));
}

#define LDSM4(r0, r1, r2, r3, addr)                                             \
    asm volatile("ldmatrix.sync.aligned.m8n8.x4.shared.b16 {%0,%1,%2,%3}, [%4];" \
                 : "=r"(r0), "=r"(r1), "=r"(r2), "=r"(r3) : "r"(addr))

#define MBARRIER_INIT(addr, cnt) \
    asm volatile("mbarrier.init.shared.b64 [%0], %1;" :: "r"(addr), "r"(cnt) : "memory")

#define MBARRIER_EXPECT_TX(addr, tx) \
    asm volatile("mbarrier.arrive.expect_tx.shared.b64 _, [%0], %1;" :: "r"(addr), "r"(tx) : "memory")

#define MBARRIER_WAIT_PARITY(addr, par) do {                                          \
    uint32_t _m = (addr), _p = (par), _done;                                          \
    asm volatile("{\n\t.reg .pred p;\n\t"                                             \
        "mbarrier.try_wait.parity.acquire.cta.shared::cta.b64 p, [%1], %2;\n\t"       \
        "selp.b32 %0, 1, 0, p;\n\t}" : "=r"(_done) : "r"(_m), "r"(_p) : "memory");    \
    if (!_done) {                                                                     \
        asm volatile("{\n\t.reg .pred P1;\n\t"                                        \
            "WL_%=:\n\t"                                                              \
            "mbarrier.try_wait.parity.acquire.cta.shared::cta.b64 P1, [%0], %1, 0x989680;\n\t" \
            "@P1 bra.uni WD_%=;\n\t"                                                  \
            "bra.uni WL_%=;\n\t"                                                      \
            "WD_%=:\n\t}" :: "r"(_m), "r"(_p) : "memory");                            \
    }                                                                                 \
} while (0)

#define BULK_G2S(dst, src, bytes, mbar)                                                        \
    asm volatile("cp.async.bulk.shared::cluster.global.mbarrier::complete_tx::bytes "          \
                 "[%0], [%1], %2, [%3];"                                                       \
                 :: "r"(dst), "l"(src), "r"(bytes), "r"(mbar) : "memory")

// ---------------------------------------------------------------------------
// fp16 mma.sync GEMM on TILED operands: D[m,n] = alpha*sum_k A[m,k]*B[n,k] (+bias)(+res)
// A: [M,K] tiled (KtA tiles/row-block); B: [N,K] tiled (KtB). Block tile 128x128,
// 256 threads (8 warps, 2x4 grid of 64x32 warp tiles), chunk fill via
// cp.async.bulk (4x8KB) + mbarrier, 3-stage, 2 CTAs/SM. ldmatrix frag loads.
// OUTM: 0 = fp32 plain row-major (+res); 1 = half tiled (KtO); 2 = half tiled
// split q|k (cols < 512 -> out0, else out1).
// M%128==0, N%128==0, K%64==0, K/64 >= STAGES-1.
// ---------------------------------------------------------------------------
template <int OUTM, bool BROW, bool BCOL, bool RES>
__global__ void __launch_bounds__(256, 2) hgemm(
    const __half* __restrict__ A, const __half* __restrict__ B,
    const float* __restrict__ bias, const float* __restrict__ res,
    void* __restrict__ out0, void* __restrict__ out1,
    int M, int N, int K, int KtA, int KtB, int KtO, float alpha,
    size_t sA, size_t sB, size_t sC, size_t sRes) {
    extern __shared__ __half smh[];
    const int tid = threadIdx.x;
    const int wid = tid >> 5, lane = tid & 31;
    const int wm = wid >> 2, wn = wid & 3;      // warp grid 2 (M) x 4 (N)
    const int gq = lane >> 2, tq = lane & 3;    // quad decomposition
    const int lj = lane >> 3, lr = lane & 7;    // ldmatrix matrix id / row
    const int bm = blockIdx.y * BM;
    const int bn = blockIdx.x * BN;
    const int z = blockIdx.z;

    const char* Ab = (const char*)(A + (size_t)z * sA);
    const char* Bb = (const char*)(B + (size_t)z * sB);
    if (RES) res += (size_t)z * sRes;

    const uint32_t sb = smem_u32(smh);
    const int bmt = bm >> 6, bnt = bn >> 6;
    const int nchunk = K / BKH;

    // lane constants for ldmatrix addressing (within 64x64 swizzled tiles)
    const int arow = (lj & 1) * 8 + lr;
    const uint32_t acolb = (uint32_t)((lj >> 1) * 16);
    const int brow = (lj >> 1) * 8 + lr;
    const uint32_t bcolb = (uint32_t)((lj & 1) * 16);

    // one-thread chunk issue: 2 A tiles + 2 B tiles, 8KB bulk each
    auto issue = [&](int s, int c) {
        const uint32_t mb = sb + s * 8;
        MBARRIER_EXPECT_TX(mb, (uint32_t)CHUNK_B);
        const uint32_t dst = sb + 128 + s * CHUNK_B;
#pragma unroll
        for (int i = 0; i < 2; i++)
            BULK_G2S(dst + i * TILE_B, Ab + ((size_t)(bmt + i) * KtA + c) * TILE_B,
                     (uint32_t)TILE_B, mb);
#pragma unroll
        for (int j = 0; j < 2; j++)
            BULK_G2S(dst + 2 * TILE_B + j * TILE_B, Bb + ((size_t)(bnt + j) * KtB + c) * TILE_B,
                     (uint32_t)TILE_B, mb);
    };

    if (tid == 0) {
#pragma unroll
        for (int s = 0; s < STAGES; s++) MBARRIER_INIT(sb + s * 8, 1);
        asm volatile("fence.proxy.async.shared::cta;" ::: "memory");
    }
    __syncthreads();
    if (tid == 0) {
        for (int s = 0; s < STAGES - 1 && s < nchunk; s++) issue(s, s);
    }

    float acc[4][4][4];
#pragma unroll
    for (int i = 0; i < 4; i++)
#pragma unroll
        for (int j = 0; j < 4; j++)
#pragma unroll
            for (int l = 0; l < 4; l++) acc[i][j][l] = 0.f;

    uint32_t af[4][4], bf[4][2];

    for (int c = 0; c < nchunk; c++) {
        const int s = c % STAGES;
        MBARRIER_WAIT_PARITY(sb + s * 8, (c / STAGES) & 1);
        __syncthreads();
        if (tid == 0 && c + STAGES - 1 < nchunk) issue((c + STAGES - 1) % STAGES, c + STAGES - 1);

        const uint32_t sstage = sb + 128 + s * CHUNK_B;
        const uint32_t stA = sstage + ((uint32_t)wm << 13);
        const uint32_t stB = sstage + 2 * TILE_B + ((uint32_t)(wn >> 1) << 13);
        const int nbase = (wn & 1) * 32;
#pragma unroll
        for (int kk = 0; kk < 4; kk++) {
            const uint32_t kkc = (uint32_t)(kk * 32);
#pragma unroll
            for (int ms = 0; ms < 4; ms++) {
                const int mrow = ms * 16 + arow;
                const uint32_t ad = stA + ((uint32_t)mrow << 7)
                                    + ((kkc + acolb) ^ ((uint32_t)(mrow & 7) << 4));
                LDSM4(af[ms][0], af[ms][1], af[ms][2], af[ms][3], ad);
            }
#pragma unroll
            for (int p = 0; p < 2; p++) {
                const int nrow = nbase + p * 16 + brow;
                const uint32_t bd = stB + ((uint32_t)nrow << 7)
                                    + ((kkc + bcolb) ^ ((uint32_t)(nrow & 7) << 4));
                LDSM4(bf[2 * p][0], bf[2 * p][1], bf[2 * p + 1][0], bf[2 * p + 1][1], bd);
            }
#pragma unroll
            for (int ms = 0; ms < 4; ms++)
#pragma unroll
                for (int ns = 0; ns < 4; ns++) mma16(acc[ms][ns], af[ms], bf[ns]);
        }
    }

    // epilogue
    float* Cf = (float*)out0 + (size_t)z * sC;
    char* C0 = (char*)((__half*)out0 + (size_t)z * sC);
    char* C1 = (OUTM == 2) ? (char*)((__half*)out1 + (size_t)z * sC) : nullptr;

#pragma unroll
    for (int ms = 0; ms < 4; ms++) {
        const int r0 = bm + wm * 64 + ms * 16 + gq;
        const int r1 = r0 + 8;
        const float bv0 = BROW ? bias[r0] : 0.f;
        const float bv1 = BROW ? bias[r1] : 0.f;
#pragma unroll
        for (int ns = 0; ns < 4; ns++) {
            const int col = bn + (wn & 3) * 32 + ns * 8 + tq * 2;
            float2 o0, o1;
            o0.x = alpha * acc[ms][ns][0] + bv0;
            o0.y = alpha * acc[ms][ns][1] + bv0;
            o1.x = alpha * acc[ms][ns][2] + bv1;
            o1.y = alpha * acc[ms][ns][3] + bv1;
            if (BCOL) {
                const float bc0 = bias[col], bc1 = bias[col + 1];
                o0.x += bc0; o0.y += bc1;
                o1.x += bc0; o1.y += bc1;
            }
            if (RES) {
                const float2 q0 = *reinterpret_cast<const float2*>(&res[(size_t)r0 * N + col]);
                const float2 q1 = *reinterpret_cast<const float2*>(&res[(size_t)r1 * N + col]);
                o0.x += q0.x; o0.y += q0.y;
                o1.x += q1.x; o1.y += q1.y;
            }
            if (OUTM == 0) {
                *reinterpret_cast<float2*>(&Cf[(size_t)r0 * N + col]) = o0;
                *reinterpret_cast<float2*>(&Cf[(size_t)r1 * N + col]) = o1;
            } else if (OUTM == 1) {
                const __half2 h0 = __floats2half2_rn(o0.x, o0.y);
                const __half2 h1 = __floats2half2_rn(o1.x, o1.y);
                *reinterpret_cast<uint32_t*>(C0 + toff(r0, col, KtO)) = *(const uint32_t*)&h0;
                *reinterpret_cast<uint32_t*>(C0 + toff(r1, col, KtO)) = *(const uint32_t*)&h1;
            } else {
                char* dst = (col < C) ? C0 : C1;
                const int k = (col < C) ? col : col - C;
                const __half2 h0 = __floats2half2_rn(o0.x, o0.y);
                const __half2 h1 = __floats2half2_rn(o1.x, o1.y);
                *reinterpret_cast<uint32_t*>(dst + toff(r0, k, KtO)) = *(const uint32_t*)&h0;
                *reinterpret_cast<uint32_t*>(dst + toff(r1, k, KtO)) = *(const uint32_t*)&h1;
            }
        }
    }
}

// ---------------------------------------------------------------------------
// weights -> fp16 tiled: combined [qw;kw] (2C x C), vw, pw (C x C)
// ---------------------------------------------------------------------------
__global__ void __launch_bounds__(256) conv_w(const float* __restrict__ qw,
                                              const float* __restrict__ kw,
                                              const float* __restrict__ vw,
                                              const float* __restrict__ pw,
                                              __half* __restrict__ qkw,
                                              __half* __restrict__ vwt,
                                              __half* __restrict__ pwt) {
    const int u = blockIdx.x * 256 + threadIdx.x;  // 131072 units of 8 halves
    const float* src;
    char* dstb;
    int r, c;
    if (u < 65536) {
        r = u >> 6; c = (u & 63) * 8;
        src = (r < C) ? (qw + (size_t)r * C + c) : (kw + (size_t)(r - C) * C + c);
        dstb = (char*)qkw;
    } else if (u < 98304) {
        const int v = u - 65536;
        r = v >> 6; c = (v & 63) * 8;
        src = vw + (size_t)r * C + c;
        dstb = (char*)vwt;
    } else {
        const int v = u - 98304;
        r = v >> 6; c = (v & 63) * 8;
        src = pw + (size_t)r * C + c;
        dstb = (char*)pwt;
    }
    const float4 f0 = *reinterpret_cast<const float4*>(src);
    const float4 f1 = *reinterpret_cast<const float4*>(src + 4);
    __half2 h[4];
    h[0] = __floats2half2_rn(f0.x, f0.y);
    h[1] = __floats2half2_rn(f0.z, f0.w);
    h[2] = __floats2half2_rn(f1.x, f1.y);
    h[3] = __floats2half2_rn(f1.z, f1.w);
    *reinterpret_cast<uint4*>(dstb + toff(r, c, 8)) = *reinterpret_cast<const uint4*>(h);
}

__global__ void qkb_kernel(const float* __restrict__ qb, const float* __restrict__ kb,
                           float* __restrict__ o) {
    const int i = threadIdx.x;  // 512
    o[i] = qb[i];
    o[C + i] = kb[i];
}

// ---------------------------------------------------------------------------
// GroupNorm -> tiled fp16 hT [HW, C]
// ---------------------------------------------------------------------------
__global__ void __launch_bounds__(512) gn_kernel(const float* __restrict__ x,
                                                 const float* __restrict__ w,
                                                 const float* __restrict__ b,
                                                 __half* __restrict__ hT) {
    const int batch = blockIdx.x / G;
    const int g = blockIdx.x % G;
    const float* xp = x + ((size_t)batch * C + (size_t)g * CPG) * HW;
    char* dstb = (char*)(hT + (size_t)batch * HW * C);

    float sum = 0.f, sq = 0.f;
    for (int i = threadIdx.x; i < CPG * HW; i += blockDim.x) {
        const float v = xp[i];
        sum += v; sq += v * v;
    }
    __shared__ float s1[32], s2[32];
#pragma unroll
    for (int o = 16; o; o >>= 1) {
        sum += __shfl_xor_sync(~0u, sum, o);
        sq += __shfl_xor_sync(~0u, sq, o);
    }
    const int lane = threadIdx.x & 31, wid = threadIdx.x >> 5;
    if (lane == 0) { s1[wid] = sum; s2[wid] = sq; }
    __syncthreads();
    if (wid == 0) {
        sum = lane < 16 ? s1[lane] : 0.f;
        sq = lane < 16 ? s2[lane] : 0.f;
#pragma unroll
        for (int o = 16; o; o >>= 1) {
            sum += __shfl_xor_sync(~0u, sum, o);
            sq += __shfl_xor_sync(~0u, sq, o);
        }
        if (lane == 0) {
            const float inv_n = 1.f / (float)(CPG * HW);
            const float m = sum * inv_n;
            const float var = sq * inv_n - m * m;
            s1[0] = m;
            s2[0] = rsqrtf(var + EPS);
        }
    }
    __syncthreads();
    const float m = s1[0], r = s2[0];

    float ws[CPG], bs[CPG];
#pragma unroll
    for (int j = 0; j < CPG; j++) {
        const float wj = w[g * CPG + j];
        ws[j] = wj * r;
        bs[j] = b[g * CPG + j] - m * wj * r;
    }
    for (int p = threadIdx.x; p < HW; p += blockDim.x) {
        __half2 o[CPG / 2];
#pragma unroll
        for (int j = 0; j < CPG; j += 2)
            o[j / 2] = __floats2half2_rn(xp[(size_t)j * HW + p] * ws[j] + bs[j],
                                         xp[(size_t)(j + 1) * HW + p] * ws[j + 1] + bs[j + 1]);
        *reinterpret_cast<uint4*>(dstb + toff(p, g * CPG, 8)) =
            *reinterpret_cast<const uint4*>(&o[0]);
        *reinterpret_cast<uint4*>(dstb + toff(p, g * CPG + 8, 8)) =
            *reinterpret_cast<const uint4*>(&o[4]);
    }
}

// ---------------------------------------------------------------------------
// Row softmax over 4096 fp16 scores in TILED layout, in place (fp32 math).
// ---------------------------------------------------------------------------
__global__ void __launch_bounds__(256) softmax_kernel(__half* __restrict__ at) {
    const int b = blockIdx.x / HW;
    const int r = blockIdx.x % HW;
    char* base = (char*)(at + (size_t)b * HW * HW);
    const uint32_t rowblk = (uint32_t)(r >> 6) * 64;
    uint32_t inner = ((uint32_t)(r & 63) << 7);
    const int t = threadIdx.x;

    uint32_t offs[2];
    uint4 u[2];
#pragma unroll
    for (int i = 0; i < 2; i++) {
        const int un = t + i * 256;                 // unit 0..511
        const uint32_t in16 = inner + (uint32_t)(un & 7) * 16;
        offs[i] = ((rowblk + (uint32_t)(un >> 3)) << 13) + (in16 ^ ((in16 >> 3) & 0x70));
        u[i] = *reinterpret_cast<const uint4*>(base + offs[i]);
    }
    float v[16];
#pragma unroll
    for (int i = 0; i < 2; i++) {
        const __half2* h = reinterpret_cast<const __half2*>(&u[i]);
#pragma unroll
        for (int j = 0; j < 4; j++) {
            const float2 f = __half22float2(h[j]);
            v[i * 8 + j * 2] = f.x;
            v[i * 8 + j * 2 + 1] = f.y;
        }
    }
    float mx = -1e30f;
#pragma unroll
    for (int i = 0; i < 16; i++) mx = fmaxf(mx, v[i]);
    __shared__ float shm[8], shs[8];
#pragma unroll
    for (int o = 16; o; o >>= 1) mx = fmaxf(mx, __shfl_xor_sync(~0u, mx, o));
    const int lane = t & 31, wid = t >> 5;
    if (lane == 0) shm[wid] = mx;
    __syncthreads();
    mx = shm[0];
#pragma unroll
    for (int i = 1; i < 8; i++) mx = fmaxf(mx, shm[i]);
    float sum = 0.f;
#pragma unroll
    for (int i = 0; i < 16; i++) { v[i] = __expf(v[i] - mx); sum += v[i]; }
#pragma unroll
    for (int o = 16; o; o >>= 1) sum += __shfl_xor_sync(~0u, sum, o);
    if (lane == 0) shs[wid] = sum;
    __syncthreads();
    sum = 0.f;
#pragma unroll
    for (int i = 0; i < 8; i++) sum += shs[i];
    const float inv = 1.f / sum;
#pragma unroll
    for (int i = 0; i < 2; i++) {
        __half2* h = reinterpret_cast<__half2*>(&u[i]);
#pragma unroll
        for (int j = 0; j < 4; j++)
            h[j] = __floats2half2_rn(v[i * 8 + j * 2] * inv, v[i * 8 + j * 2 + 1] * inv);
        *reinterpret_cast<uint4*>(base + offs[i]) = u[i];
    }
}

// ---------------------------------------------------------------------------
extern "C" void kernel_launch(void* const* d_in, const int* in_sizes, int n_in,
                              void* d_out, int out_size) {
    const float* x   = (const float*)d_in[0];
    const float* gnw = (const float*)d_in[1];
    const float* gnb = (const float*)d_in[2];
    const float* qw  = (const float*)d_in[3];
    const float* qb  = (const float*)d_in[4];
    const float* kw  = (const float*)d_in[5];
    const float* kb  = (const float*)d_in[6];
    const float* vw  = (const float*)d_in[7];
    const float* vb  = (const float*)d_in[8];
    const float* pw  = (const float*)d_in[9];
    const float* pb  = (const float*)d_in[10];
    float* out = (float*)d_out;

    __half *hth, *qt, *kt, *vh, *at, *oth, *qkw, *vwt, *pwt;
    float *qkb;
    cudaGetSymbolAddress((void**)&hth, g_hth);
    cudaGetSymbolAddress((void**)&qt, g_qt);
    cudaGetSymbolAddress((void**)&kt, g_kt);
    cudaGetSymbolAddress((void**)&vh, g_vh);
    cudaGetSymbolAddress((void**)&at, g_at);
    cudaGetSymbolAddress((void**)&oth, g_oth);
    cudaGetSymbolAddress((void**)&qkw, g_qkw);
    cudaGetSymbolAddress((void**)&vwt, g_vwt);
    cudaGetSymbolAddress((void**)&pwt, g_pwt);
    cudaGetSymbolAddress((void**)&qkb, g_qkb);

    cudaFuncSetAttribute(hgemm<2, false, true,  false>, cudaFuncAttributeMaxDynamicSharedMemorySize, SMEM_BYTES);
    cudaFuncSetAttribute(hgemm<1, true,  false, false>, cudaFuncAttributeMaxDynamicSharedMemorySize, SMEM_BYTES);
    cudaFuncSetAttribute(hgemm<1, false, false, false>, cudaFuncAttributeMaxDynamicSharedMemorySize, SMEM_BYTES);
    cudaFuncSetAttribute(hgemm<0, true,  false, true >, cudaFuncAttributeMaxDynamicSharedMemorySize, SMEM_BYTES);

    const size_t sHC = (size_t)HW * C;
    const size_t sS = (size_t)HW * HW;
    const float scale = 0.044194173824159216f;  // 512^-0.5

    // 0) tiled fp16 weights + combined qk bias; 1) GroupNorm -> tiled hT
    conv_w<<<512, 256>>>(qw, kw, vw, pw, qkw, vwt, pwt);
    qkb_kernel<<<1, C>>>(qb, kb, qkb);
    gn_kernel<<<BATCH * G, 512>>>(x, gnw, gnb, hth);

    dim3 blk(256);
    // 2) [q|k] = hT @ [qw;kw]^T + bias(col):  M=HW, N=2C, K=C -> qt, kt tiled
    dim3 g1(2 * C / BN, HW / BM, BATCH);
    hgemm<2, false, true, false><<<g1, blk, SMEM_BYTES>>>(
        hth, qkw, qkb, nullptr, qt, kt, HW, 2 * C, C, 8, 8, 8, 1.f, sHC, 0, sHC, 0);
    //    v = vw @ h + bias(row):  M=C, N=HW, K=C -> vh tiled
    dim3 g2(HW / BN, C / BM, BATCH);
    hgemm<1, true, false, false><<<g2, blk, SMEM_BYTES>>>(
        vwt, hth, vb, nullptr, vh, nullptr, C, HW, C, 8, 8, 64, 1.f, 0, sHC, sHC, 0);

    // 3) scores = q @ k^T * scale:  M=HW, N=HW, K=C -> at tiled
    dim3 g3(HW / BN, HW / BM, BATCH);
    hgemm<1, false, false, false><<<g3, blk, SMEM_BYTES>>>(
        qt, kt, nullptr, nullptr, at, nullptr, HW, HW, C, 8, 8, 64, scale, sHC, sHC, sS, 0);

    // 4) softmax rows in place (tiled fp16)
    softmax_kernel<<<BATCH * HW, 256>>>(at);

    // 5) oT = attn @ v^T:  M=HW, N=C, K=HW -> oth tiled
    dim3 g5(C / BN, HW / BM, BATCH);
    hgemm<1, false, false, false><<<g5, blk, SMEM_BYTES>>>(
        at, vh, nullptr, nullptr, oth, nullptr, HW, C, HW, 64, 64, 8, 1.f, sS, sHC, sHC, 0);

    // 6) out = x + pw @ o + pb:  M=C, N=HW, K=C (fp32 plain out)
    dim3 g6(HW / BN, C / BM, BATCH);
    hgemm<0, true, false, true><<<g6, blk, SMEM_BYTES>>>(
        pwt, oth, pb, x, out, nullptr, C, HW, C, 8, 8, 0, 1.f, 0, sHC, sHC, sHC);
}